// round 8
// baseline (speedup 1.0000x reference)
#include <cuda_runtime.h>
#include <math.h>
#include <stdint.h>

#define NPTS 16384
#define MC   4096
#define DIMF 128
#define NH   4
#define DH   32
#define KNB  32
#define HID  512
#define RAD  0.3f
#define R2L  0.09000902f
#define CAP  512
#define CPB  8
#define CCH  512

// ---------------- scratch ----------------
__device__ int    g_idxc[MC];
__device__ float4 g_pts[NPTS];
__device__ __align__(16) float g_Qc[MC*DIMF];
__device__ __align__(16) float g_Kp[NPTS*DIMF];
__device__ __align__(16) float g_Vp[NPTS*DIMF];
__device__ int    g_nbr[MC*KNB];
__device__ int    g_cnt[MC];
__device__ unsigned long long g_nearKey[NPTS];
__device__ __align__(16) float g_ao[MC*DIMF];
__device__ __align__(16) float g_c1[MC*DIMF];
__device__ __align__(16) float g_hid[MC*HID];
__device__ __align__(16) float g_c2[MC*DIMF];

// ---------------- init ----------------
__global__ void k_init(const float* __restrict__ xyz, const long long* __restrict__ raw) {
    int n = blockIdx.x * 256 + threadIdx.x;
    float x = xyz[3*n], y = xyz[3*n+1], z = xyz[3*n+2];
    g_pts[n] = make_float4(x, y, z, x*x + y*y + z*z);
    g_nearKey[n] = ~0ull;
    if (blockIdx.x == 0) {
        __shared__ int s_ok;
        if (threadIdx.x == 0) s_ok = 1;
        __syncthreads();
        for (int m = threadIdx.x; m < MC/2; m += 256) {
            long long v = raw[m];
            if (v < 0 || v >= NPTS) s_ok = 0;
        }
        __syncthreads();
        if (s_ok) {
            for (int m = threadIdx.x; m < MC; m += 256)
                g_idxc[m] = (int)raw[m];
        } else {
            const int* r32 = (const int*)raw;
            for (int m = threadIdx.x; m < MC; m += 256)
                g_idxc[m] = r32[m];
        }
    }
}

// ---------------- per-center radius filter + exact top-K ----------------
__global__ __launch_bounds__(256) void k_topk() {
    __shared__ float cd[CPB][CAP];
    __shared__ int   ci[CPB][CAP];
    __shared__ int   s_cnt[CPB];
    const int tid = threadIdx.x;
    const int m0 = blockIdx.x * CPB;
    if (tid < CPB) s_cnt[tid] = 0;
    __syncthreads();

    float cx2[CPB], cy2[CPB], cz2[CPB], cc[CPB];
    #pragma unroll
    for (int g = 0; g < CPB; g++) {
        float4 c = g_pts[g_idxc[m0 + g]];
        cx2[g] = -2.f*c.x; cy2[g] = -2.f*c.y; cz2[g] = -2.f*c.z; cc[g] = c.w;
    }
    __syncthreads();

    for (int n = tid; n < NPTS; n += 256) {
        float4 p = g_pts[n];
        float rhs = R2L - p.w;
        #pragma unroll
        for (int g = 0; g < CPB; g++) {
            float t = fmaf(cx2[g], p.x, cc[g]);
            t = fmaf(cy2[g], p.y, t);
            t = fmaf(cz2[g], p.z, t);
            if (t < rhs) {
                float dist = sqrtf(fmaxf(t + p.w, 1e-12f));
                if (dist < RAD) {
                    int q = atomicAdd(&s_cnt[g], 1);
                    if (q < CAP) { cd[g][q] = dist; ci[g][q] = n; }
                }
            }
        }
    }
    __syncthreads();

    #pragma unroll
    for (int g = 0; g < CPB; g++) {
        int cnt = min(s_cnt[g], CAP);
        int m = m0 + g;
        for (int c = tid; c < cnt; c += 256) {
            float d = cd[g][c]; int i = ci[g][c];
            int rank = 0;
            for (int j = 0; j < cnt; j++) {
                float dj = cd[g][j];
                rank += (dj < d) || (dj == d && ci[g][j] < i);
            }
            if (rank < KNB) g_nbr[m*KNB + rank] = i;
        }
        int v = min(cnt, KNB);
        if (tid == 0) g_cnt[m] = v;
        if (tid >= v && tid < KNB) g_nbr[m*KNB + tid] = 0;
    }
}

// ---------------- per-point nearest center ----------------
__global__ __launch_bounds__(256) void k_nearest() {
    __shared__ float4 sc[CCH];
    const int tid = threadIdx.x;
    const int nb = blockIdx.x * 1024 + tid;
    const int base = blockIdx.y * CCH;
    for (int j = tid; j < CCH; j += 256)
        sc[j] = g_pts[g_idxc[base + j]];
    float4 p0 = g_pts[nb], p1 = g_pts[nb+256], p2 = g_pts[nb+512], p3 = g_pts[nb+768];
    __syncthreads();
    float b0 = 3.4e38f, b1 = 3.4e38f, b2 = 3.4e38f, b3 = 3.4e38f;
    int i0 = 0, i1 = 0, i2 = 0, i3 = 0;
    #pragma unroll 4
    for (int j = 0; j < CCH; j++) {
        float4 c = sc[j];
        float d0 = fmaf(-2.f, fmaf(c.x, p0.x, fmaf(c.y, p0.y, c.z*p0.z)), c.w);
        float d1 = fmaf(-2.f, fmaf(c.x, p1.x, fmaf(c.y, p1.y, c.z*p1.z)), c.w);
        float d2 = fmaf(-2.f, fmaf(c.x, p2.x, fmaf(c.y, p2.y, c.z*p2.z)), c.w);
        float d3 = fmaf(-2.f, fmaf(c.x, p3.x, fmaf(c.y, p3.y, c.z*p3.z)), c.w);
        if (d0 < b0) { b0 = d0; i0 = j; }
        if (d1 < b1) { b1 = d1; i1 = j; }
        if (d2 < b2) { b2 = d2; i2 = j; }
        if (d3 < b3) { b3 = d3; i3 = j; }
    }
    unsigned long long k0 = ((unsigned long long)__float_as_uint(fmaxf(b0 + p0.w, 0.f)) << 32) | (unsigned)(base + i0);
    unsigned long long k1 = ((unsigned long long)__float_as_uint(fmaxf(b1 + p1.w, 0.f)) << 32) | (unsigned)(base + i1);
    unsigned long long k2 = ((unsigned long long)__float_as_uint(fmaxf(b2 + p2.w, 0.f)) << 32) | (unsigned)(base + i2);
    unsigned long long k3 = ((unsigned long long)__float_as_uint(fmaxf(b3 + p3.w, 0.f)) << 32) | (unsigned)(base + i3);
    atomicMin(&g_nearKey[nb],     k0);
    atomicMin(&g_nearKey[nb+256], k1);
    atomicMin(&g_nearKey[nb+512], k2);
    atomicMin(&g_nearKey[nb+768], k3);
}

// ---------------- TF32 GEMM helpers ----------------
__device__ __forceinline__ uint32_t cvt_tf32(float x) {
    uint32_t r;
    asm("cvt.rna.tf32.f32 %0, %1;" : "=r"(r) : "f"(x));
    return r;
}
__device__ __forceinline__ uint32_t smem_u32(const void* p) {
    return (uint32_t)__cvta_generic_to_shared(p);
}
__device__ __forceinline__ void cp_async16(uint32_t dst, const float* src) {
    asm volatile("cp.async.cg.shared.global [%0], [%1], 16;\n" :: "r"(dst), "l"(src));
}
__device__ __forceinline__ void cp_commit() { asm volatile("cp.async.commit_group;\n"); }
template<int N> __device__ __forceinline__ void cp_wait() {
    asm volatile("cp.async.wait_group %0;\n" :: "n"(N));
}
#define MMA_TF32(acc, a0,a1,a2,a3, b0,b1) \
    asm volatile( \
        "mma.sync.aligned.m16n8k8.row.col.f32.tf32.tf32.f32 " \
        "{%0,%1,%2,%3}, {%4,%5,%6,%7}, {%8,%9}, {%0,%1,%2,%3};\n" \
        : "+f"((acc)[0]), "+f"((acc)[1]), "+f"((acc)[2]), "+f"((acc)[3]) \
        : "r"(a0), "r"(a1), "r"(a2), "r"(a3), "r"(b0), "r"(b1))

// LNMODE: 0 = bias/relu epilogue; 1 = bias -> LayerNorm + residual
// GATHERA: A row r comes from A[rowIdx[r]]
template<int BM, int BN, int WM, int WN, int LNMODE, int GATHERA>
__device__ __forceinline__ void gemm_body(
    const float* __restrict__ A, const float* __restrict__ W,
    const float* __restrict__ bias, float* __restrict__ C,
    int Cin, int Cout, int relu,
    const float* __restrict__ lng, const float* __restrict__ lnb,
    const float* __restrict__ resid, int gatherResid,
    const int* __restrict__ rowIdx)
{
    constexpr int BK = 16;
    constexpr int LDK = BK + 4;
    constexpr int MT = WM / 16, NT = WN / 8;
    constexpr int WCOLS = BN / WN;
    extern __shared__ __align__(16) char dsm[];
    float (*As)[BM][LDK] = reinterpret_cast<float(*)[BM][LDK]>(dsm);
    float (*Ws)[BN][LDK] = reinterpret_cast<float(*)[BN][LDK]>(dsm + 2*BM*LDK*sizeof(float));

    const int tid = threadIdx.x;
    const int wid = tid >> 5, lane = tid & 31;
    const int wmBase = (wid / WCOLS) * WM;
    const int wnBase = (wid % WCOLS) * WN;
    const int rowBase = blockIdx.x * BM;
    const int colBase = blockIdx.y * BN;
    const int lr = lane >> 2, lc = lane & 3;

    float acc[MT][NT][4];
    #pragma unroll
    for (int i = 0; i < MT; i++)
        #pragma unroll
        for (int j = 0; j < NT; j++)
            #pragma unroll
            for (int q = 0; q < 4; q++) acc[i][j][q] = 0.f;

    auto copy_tile = [&](int st, int k0) {
        #pragma unroll
        for (int f = tid; f < BM * (BK/4); f += 256) {
            int row = f >> 2, kq = f & 3;
            int ar = GATHERA ? rowIdx[rowBase + row] : (rowBase + row);
            cp_async16(smem_u32(&As[st][row][kq*4]),
                       A + (size_t)ar*Cin + k0 + kq*4);
        }
        #pragma unroll
        for (int f = tid; f < BN * (BK/4); f += 256) {
            int row = f >> 2, kq = f & 3;
            cp_async16(smem_u32(&Ws[st][row][kq*4]),
                       W + (size_t)(colBase + row)*Cin + k0 + kq*4);
        }
    };

    const int NTILES = Cin / BK;
    copy_tile(0, 0);
    cp_commit();

    for (int t = 0; t < NTILES; t++) {
        const int st = t & 1;
        if (t + 1 < NTILES) { copy_tile(st ^ 1, (t+1)*BK); cp_commit(); cp_wait<1>(); }
        else cp_wait<0>();
        __syncthreads();

        #pragma unroll
        for (int ks = 0; ks < BK/8; ks++) {
            uint32_t bfr[NT][2];
            #pragma unroll
            for (int nt = 0; nt < NT; nt++) {
                int nn = wnBase + nt*8 + lr;
                bfr[nt][0] = cvt_tf32(Ws[st][nn][ks*8 + lc]);
                bfr[nt][1] = cvt_tf32(Ws[st][nn][ks*8 + lc + 4]);
            }
            uint32_t afr[MT][4];
            #pragma unroll
            for (int mt = 0; mt < MT; mt++) {
                int rr = wmBase + mt*16 + lr;
                afr[mt][0] = cvt_tf32(As[st][rr][ks*8 + lc]);
                afr[mt][1] = cvt_tf32(As[st][rr + 8][ks*8 + lc]);
                afr[mt][2] = cvt_tf32(As[st][rr][ks*8 + lc + 4]);
                afr[mt][3] = cvt_tf32(As[st][rr + 8][ks*8 + lc + 4]);
            }
            #pragma unroll
            for (int mt = 0; mt < MT; mt++)
                #pragma unroll
                for (int nt = 0; nt < NT; nt++)
                    MMA_TF32(acc[mt][nt], afr[mt][0], afr[mt][1], afr[mt][2], afr[mt][3],
                             bfr[nt][0], bfr[nt][1]);
        }
        __syncthreads();
    }

    if (LNMODE == 0) {
        #pragma unroll
        for (int mt = 0; mt < MT; mt++) {
            #pragma unroll
            for (int nt = 0; nt < NT; nt++) {
                int row0 = rowBase + wmBase + mt*16 + lr;
                int col  = colBase + wnBase + nt*8 + 2*lc;
                float bx = 0.f, by = 0.f;
                if (bias) { bx = bias[col]; by = bias[col+1]; }
                float2 o0 = make_float2(acc[mt][nt][0] + bx, acc[mt][nt][1] + by);
                float2 o1 = make_float2(acc[mt][nt][2] + bx, acc[mt][nt][3] + by);
                if (relu) {
                    o0.x = fmaxf(o0.x, 0.f); o0.y = fmaxf(o0.y, 0.f);
                    o1.x = fmaxf(o1.x, 0.f); o1.y = fmaxf(o1.y, 0.f);
                }
                *reinterpret_cast<float2*>(C + (size_t)row0*Cout + col) = o0;
                *reinterpret_cast<float2*>(C + (size_t)(row0+8)*Cout + col) = o1;
            }
        }
    } else {
        float (*Cs)[BN + 4] = reinterpret_cast<float(*)[BN + 4]>(dsm);
        #pragma unroll
        for (int mt = 0; mt < MT; mt++) {
            #pragma unroll
            for (int nt = 0; nt < NT; nt++) {
                int r0 = wmBase + mt*16 + lr;
                int col = wnBase + nt*8 + 2*lc;
                float bx = bias[col], by = bias[col+1];
                *reinterpret_cast<float2*>(&Cs[r0][col]) =
                    make_float2(acc[mt][nt][0] + bx, acc[mt][nt][1] + by);
                *reinterpret_cast<float2*>(&Cs[r0 + 8][col]) =
                    make_float2(acc[mt][nt][2] + bx, acc[mt][nt][3] + by);
            }
        }
        __syncthreads();
        #pragma unroll
        for (int r = 0; r < BM/8; r++) {
            int row = wid * (BM/8) + r;
            float4 v = *reinterpret_cast<float4*>(&Cs[row][lane*4]);
            float s = v.x + v.y + v.z + v.w;
            float q = v.x*v.x + v.y*v.y + v.z*v.z + v.w*v.w;
            #pragma unroll
            for (int o = 16; o > 0; o >>= 1) {
                s += __shfl_xor_sync(0xffffffffu, s, o);
                q += __shfl_xor_sync(0xffffffffu, q, o);
            }
            float mu = s * (1.f/DIMF);
            float var = fmaxf(q * (1.f/DIMF) - mu*mu, 0.f);
            float rstd = rsqrtf(var + 1e-5f);
            int grow = rowBase + row;
            int rrow = gatherResid ? g_idxc[grow] : grow;
            float4 gv = *reinterpret_cast<const float4*>(lng + lane*4);
            float4 bv = *reinterpret_cast<const float4*>(lnb + lane*4);
            float4 rv = *reinterpret_cast<const float4*>(resid + (size_t)rrow*DIMF + lane*4);
            float4 o;
            o.x = (v.x - mu) * rstd * gv.x + bv.x + rv.x;
            o.y = (v.y - mu) * rstd * gv.y + bv.y + rv.y;
            o.z = (v.z - mu) * rstd * gv.z + bv.z + rv.z;
            o.w = (v.w - mu) * rstd * gv.w + bv.w + rv.w;
            *reinterpret_cast<float4*>(C + (size_t)grow*DIMF + lane*4) = o;
        }
    }
}

template<int BM, int BN, int WM, int WN>
__global__ __launch_bounds__(256, 3) void k_gemm_ln(
    const float* __restrict__ A, const float* __restrict__ W,
    const float* __restrict__ bias, float* __restrict__ C, int Cin,
    const float* __restrict__ lng, const float* __restrict__ lnb,
    const float* __restrict__ resid, int gatherResid)
{
    gemm_body<BM, BN, WM, WN, 1, 0>(A, W, bias, C, Cin, DIMF, 0,
                                    lng, lnb, resid, gatherResid, nullptr);
}

// QKV merged: z=0 -> K, z=1 -> V (all points); z=2 -> Q over gathered centers
struct P3 { const float* W[3]; float* C[3]; };
__global__ __launch_bounds__(256, 3) void k_gemm_qkv(const float* __restrict__ A, P3 p)
{
    int z = blockIdx.z;
    if (z == 2) {
        if (blockIdx.x >= MC/64) return;
        gemm_body<64, 128, 32, 32, 0, 1>(A, p.W[2], nullptr, p.C[2], DIMF, DIMF, 0,
                                         nullptr, nullptr, nullptr, 0, g_idxc);
    } else {
        gemm_body<64, 128, 32, 32, 0, 0>(A, p.W[z], nullptr, p.C[z], DIMF, DIMF, 0,
                                         nullptr, nullptr, nullptr, 0, nullptr);
    }
}

// ---------------- fused: upd = ao@Wo^T+bo -> LN1+resid -> c1 ; hid = relu(c1@W1^T+b1)
__global__ __launch_bounds__(256, 3) void k_wo_ffn(
    const float* __restrict__ ao, const float* __restrict__ Wo,
    const float* __restrict__ bo,
    const float* __restrict__ g1, const float* __restrict__ be1,
    const float* __restrict__ feats, float* __restrict__ c1out,
    const float* __restrict__ W1, const float* __restrict__ b1f,
    float* __restrict__ hid)
{
    constexpr int BM = 32, BN = 128, BK = 16, LDK = BK + 4;
    extern __shared__ __align__(16) char dsm[];
    float (*As)[BM][LDK] = reinterpret_cast<float(*)[BM][LDK]>(dsm);
    float (*Ws)[BN][LDK] = reinterpret_cast<float(*)[BN][LDK]>(dsm + 2*BM*LDK*4);

    const int tid = threadIdx.x, wid = tid >> 5, lane = tid & 31;
    const int wmBase = (wid >> 2) * 16, wnBase = (wid & 3) * 32;
    const int rowBase = blockIdx.x * BM;
    const int lr = lane >> 2, lc = lane & 3;

    // ---- stage 1: ao @ Wo^T  (32 x 128, k=128) ----
    float acc[4][4];
    #pragma unroll
    for (int j = 0; j < 4; j++)
        #pragma unroll
        for (int q = 0; q < 4; q++) acc[j][q] = 0.f;

    auto copy1 = [&](int st, int k0) {
        #pragma unroll
        for (int f = tid; f < BM*(BK/4); f += 256) {
            int row = f >> 2, kq = f & 3;
            cp_async16(smem_u32(&As[st][row][kq*4]),
                       ao + (size_t)(rowBase+row)*DIMF + k0 + kq*4);
        }
        #pragma unroll
        for (int f = tid; f < BN*(BK/4); f += 256) {
            int row = f >> 2, kq = f & 3;
            cp_async16(smem_u32(&Ws[st][row][kq*4]),
                       Wo + (size_t)row*DIMF + k0 + kq*4);
        }
    };
    copy1(0, 0); cp_commit();
    #pragma unroll
    for (int t = 0; t < DIMF/BK; t++) {
        const int st = t & 1;
        if (t+1 < DIMF/BK) { copy1(st^1, (t+1)*BK); cp_commit(); cp_wait<1>(); }
        else cp_wait<0>();
        __syncthreads();
        #pragma unroll
        for (int ks = 0; ks < 2; ks++) {
            uint32_t bfr[4][2], afr[4];
            #pragma unroll
            for (int nt = 0; nt < 4; nt++) {
                int nn = wnBase + nt*8 + lr;
                bfr[nt][0] = cvt_tf32(Ws[st][nn][ks*8+lc]);
                bfr[nt][1] = cvt_tf32(Ws[st][nn][ks*8+lc+4]);
            }
            int rr = wmBase + lr;
            afr[0] = cvt_tf32(As[st][rr][ks*8+lc]);
            afr[1] = cvt_tf32(As[st][rr+8][ks*8+lc]);
            afr[2] = cvt_tf32(As[st][rr][ks*8+lc+4]);
            afr[3] = cvt_tf32(As[st][rr+8][ks*8+lc+4]);
            #pragma unroll
            for (int nt = 0; nt < 4; nt++)
                MMA_TF32(acc[nt], afr[0], afr[1], afr[2], afr[3], bfr[nt][0], bfr[nt][1]);
        }
        __syncthreads();
    }

    // ---- stage into Cs with bias, LN + residual -> c1 (global + smem) ----
    float (*Cs)[BN + 4] = reinterpret_cast<float(*)[BN + 4]>(dsm);
    #pragma unroll
    for (int nt = 0; nt < 4; nt++) {
        int r0 = wmBase + lr;
        int col = wnBase + nt*8 + 2*lc;
        float bx = bo[col], by = bo[col+1];
        *reinterpret_cast<float2*>(&Cs[r0][col])   = make_float2(acc[nt][0]+bx, acc[nt][1]+by);
        *reinterpret_cast<float2*>(&Cs[r0+8][col]) = make_float2(acc[nt][2]+bx, acc[nt][3]+by);
    }
    __syncthreads();
    #pragma unroll
    for (int r = 0; r < 4; r++) {
        int row = wid*4 + r;
        float4 v = *reinterpret_cast<float4*>(&Cs[row][lane*4]);
        float s = v.x+v.y+v.z+v.w;
        float q = v.x*v.x + v.y*v.y + v.z*v.z + v.w*v.w;
        #pragma unroll
        for (int o = 16; o > 0; o >>= 1) {
            s += __shfl_xor_sync(0xffffffffu, s, o);
            q += __shfl_xor_sync(0xffffffffu, q, o);
        }
        float mu = s * (1.f/DIMF);
        float var = fmaxf(q * (1.f/DIMF) - mu*mu, 0.f);
        float rstd = rsqrtf(var + 1e-5f);
        int grow = rowBase + row;
        int rrow = g_idxc[grow];
        float4 gv = *reinterpret_cast<const float4*>(g1 + lane*4);
        float4 bv = *reinterpret_cast<const float4*>(be1 + lane*4);
        float4 rv = *reinterpret_cast<const float4*>(feats + (size_t)rrow*DIMF + lane*4);
        float4 o;
        o.x = (v.x - mu) * rstd * gv.x + bv.x + rv.x;
        o.y = (v.y - mu) * rstd * gv.y + bv.y + rv.y;
        o.z = (v.z - mu) * rstd * gv.z + bv.z + rv.z;
        o.w = (v.w - mu) * rstd * gv.w + bv.w + rv.w;
        *reinterpret_cast<float4*>(c1out + (size_t)grow*DIMF + lane*4) = o;
        *reinterpret_cast<float4*>(&Cs[row][lane*4]) = o;
    }
    __syncthreads();

    // ---- stage 2: hid = relu(Cs @ W1^T + b1f)  (32 x 512, k=128) ----
    float (*Bs)[128][LDK] = reinterpret_cast<float(*)[128][LDK]>(dsm + BM*(BN+4)*4);
    for (int cy = 0; cy < 4; cy++) {
        float acc2[4][4];
        #pragma unroll
        for (int j = 0; j < 4; j++)
            #pragma unroll
            for (int q = 0; q < 4; q++) acc2[j][q] = 0.f;

        auto copy2 = [&](int st, int k0) {
            #pragma unroll
            for (int f = tid; f < 128*(BK/4); f += 256) {
                int row = f >> 2, kq = f & 3;
                cp_async16(smem_u32(&Bs[st][row][kq*4]),
                           W1 + (size_t)(cy*128+row)*DIMF + k0 + kq*4);
            }
        };
        copy2(0, 0); cp_commit();
        #pragma unroll
        for (int t = 0; t < DIMF/BK; t++) {
            const int st = t & 1;
            if (t+1 < DIMF/BK) { copy2(st^1, (t+1)*BK); cp_commit(); cp_wait<1>(); }
            else cp_wait<0>();
            __syncthreads();
            #pragma unroll
            for (int ks = 0; ks < 2; ks++) {
                uint32_t bfr[4][2], afr[4];
                #pragma unroll
                for (int nt = 0; nt < 4; nt++) {
                    int nn = wnBase + nt*8 + lr;
                    bfr[nt][0] = cvt_tf32(Bs[st][nn][ks*8+lc]);
                    bfr[nt][1] = cvt_tf32(Bs[st][nn][ks*8+lc+4]);
                }
                int rr = wmBase + lr;
                int kk = t*BK + ks*8 + lc;
                afr[0] = cvt_tf32(Cs[rr][kk]);
                afr[1] = cvt_tf32(Cs[rr+8][kk]);
                afr[2] = cvt_tf32(Cs[rr][kk+4]);
                afr[3] = cvt_tf32(Cs[rr+8][kk+4]);
                #pragma unroll
                for (int nt = 0; nt < 4; nt++)
                    MMA_TF32(acc2[nt], afr[0], afr[1], afr[2], afr[3], bfr[nt][0], bfr[nt][1]);
            }
            __syncthreads();
        }
        #pragma unroll
        for (int nt = 0; nt < 4; nt++) {
            int row0 = rowBase + wmBase + lr;
            int col = cy*128 + wnBase + nt*8 + 2*lc;
            float bx = b1f[col], by = b1f[col+1];
            float2 o0 = make_float2(fmaxf(acc2[nt][0]+bx, 0.f), fmaxf(acc2[nt][1]+by, 0.f));
            float2 o1 = make_float2(fmaxf(acc2[nt][2]+bx, 0.f), fmaxf(acc2[nt][3]+by, 0.f));
            *reinterpret_cast<float2*>(hid + (size_t)row0*HID + col) = o0;
            *reinterpret_cast<float2*>(hid + (size_t)(row0+8)*HID + col) = o1;
        }
    }
}

// smem byte counts
#define GSM(BM_, BN_) (2 * ((BM_) + (BN_)) * 20 * 4)
static const int SM_64   = GSM(64,128);                       // 30720
static const int SM_LN   = GSM(32,128) > (32*(128+4)*4) ? GSM(32,128) : (32*(128+4)*4);
static const int SM_WOFFN = 32*(128+4)*4 + 2*128*20*4;        // 16896 + 20480 = 37376

// ---------------- per-center attention ----------------
__global__ void k_attn() {
    __shared__ float q[DIMF];
    __shared__ float kS[KNB][DIMF + 4];
    __shared__ float vS[KNB][DIMF + 4];
    __shared__ int nbr_s[KNB];
    __shared__ int s_cnt;
    const int m = blockIdx.x, tid = threadIdx.x;
    if (tid < KNB) nbr_s[tid] = g_nbr[m*KNB + tid];
    if (tid == 0) s_cnt = g_cnt[m];
    q[tid] = g_Qc[(size_t)m*DIMF + tid] * 0.17677669529663687f;  // DH^-0.5
    __syncthreads();

    #pragma unroll
    for (int f = tid; f < KNB * (DIMF/4); f += 128) {
        int s = f >> 5, c4 = f & 31;
        size_t off = (size_t)nbr_s[s]*DIMF + c4*4;
        float4 kx = *reinterpret_cast<const float4*>(&g_Kp[off]);
        float4 vx = *reinterpret_cast<const float4*>(&g_Vp[off]);
        *reinterpret_cast<float4*>(&kS[s][c4*4]) = kx;
        *reinterpret_cast<float4*>(&vS[s][c4*4]) = vx;
    }
    __syncthreads();

    const int h = tid >> 5, lane = tid & 31;
    const int cnt = s_cnt;
    float logit = -1e9f;
    if (lane < cnt) {
        float a = 0.f;
        #pragma unroll
        for (int d = 0; d < DH; d++) a += q[h*DH + d] * kS[lane][h*DH + d];
        logit = a;
    }
    float mx = logit;
    #pragma unroll
    for (int o = 16; o > 0; o >>= 1) mx = fmaxf(mx, __shfl_xor_sync(0xffffffffu, mx, o));
    float e = (lane < cnt) ? expf(logit - mx) : 0.f;
    float sm = e;
    #pragma unroll
    for (int o = 16; o > 0; o >>= 1) sm += __shfl_xor_sync(0xffffffffu, sm, o);
    float w = e / sm;

    float acc = 0.f;
    #pragma unroll
    for (int kk = 0; kk < KNB; kk++)
        acc += __shfl_sync(0xffffffffu, w, kk) * vS[kk][h*DH + lane];
    g_ao[(size_t)m*DIMF + lane*NH + h] = acc;
}

// ---------------- final scatter ----------------
__global__ void k_scatter(const float* __restrict__ feats, float* __restrict__ out) {
    int i = blockIdx.x * 256 + threadIdx.x;
    int n = i >> 5, c4 = i & 31;
    int ctr = (int)(g_nearKey[n] & 0xffffffffu);
    float4 f = *reinterpret_cast<const float4*>(feats + (size_t)n*DIMF + c4*4);
    float4 c = *reinterpret_cast<const float4*>(g_c2 + (size_t)ctr*DIMF + c4*4);
    f.x += c.x; f.y += c.y; f.z += c.z; f.w += c.w;
    *reinterpret_cast<float4*>(out + (size_t)n*DIMF + c4*4) = f;
}

// ---------------- launch ----------------
extern "C" void kernel_launch(void* const* d_in, const int* in_sizes, int n_in,
                              void* d_out, int out_size) {
    const float* xyz   = (const float*)d_in[0];
    const float* feats = (const float*)d_in[1];
    const long long* idxc = (const long long*)d_in[2];
    const float* Wq = (const float*)d_in[3];
    const float* Wk = (const float*)d_in[4];
    const float* Wv = (const float*)d_in[5];
    const float* Wo = (const float*)d_in[6];
    const float* bo = (const float*)d_in[7];
    const float* g1 = (const float*)d_in[8];
    const float* be1 = (const float*)d_in[9];
    const float* g2 = (const float*)d_in[10];
    const float* be2 = (const float*)d_in[11];
    const float* W1 = (const float*)d_in[12];
    const float* b1f = (const float*)d_in[13];
    const float* W2 = (const float*)d_in[14];
    const float* b2f = (const float*)d_in[15];
    float* out = (float*)d_out;

    float *qc, *kp, *vp, *ao, *c1, *hid, *c2;
    cudaGetSymbolAddress((void**)&qc,  g_Qc);
    cudaGetSymbolAddress((void**)&kp,  g_Kp);
    cudaGetSymbolAddress((void**)&vp,  g_Vp);
    cudaGetSymbolAddress((void**)&ao,  g_ao);
    cudaGetSymbolAddress((void**)&c1,  g_c1);
    cudaGetSymbolAddress((void**)&hid, g_hid);
    cudaGetSymbolAddress((void**)&c2,  g_c2);

    static cudaStream_t s1 = nullptr, s2 = nullptr;
    static cudaEvent_t eFork = nullptr, eTopk = nullptr, eNear = nullptr;
    if (!s1) {
        cudaStreamCreateWithFlags(&s1, cudaStreamNonBlocking);
        cudaStreamCreateWithFlags(&s2, cudaStreamNonBlocking);
        cudaEventCreateWithFlags(&eFork, cudaEventDisableTiming);
        cudaEventCreateWithFlags(&eTopk, cudaEventDisableTiming);
        cudaEventCreateWithFlags(&eNear, cudaEventDisableTiming);
    }
    cudaStream_t s0 = 0;

    k_init<<<NPTS/256, 256, 0, s0>>>(xyz, idxc);
    cudaEventRecord(eFork, s0);

    cudaStreamWaitEvent(s1, eFork, 0);
    cudaStreamWaitEvent(s2, eFork, 0);
    k_topk<<<MC/CPB, 256, 0, s1>>>();
    cudaEventRecord(eTopk, s1);
    k_nearest<<<dim3(NPTS/1024, MC/CCH), 256, 0, s2>>>();
    cudaEventRecord(eNear, s2);

    P3 p;
    p.W[0] = Wk; p.W[1] = Wv; p.W[2] = Wq;
    p.C[0] = kp; p.C[1] = vp; p.C[2] = qc;
    k_gemm_qkv<<<dim3(NPTS/64, 1, 3), 256, SM_64, s0>>>(feats, p);

    cudaStreamWaitEvent(s0, eTopk, 0);
    k_attn<<<MC, 128, 0, s0>>>();

    // Wo GEMM + LN1 + residual + FFN-up fused  (128 blocks)
    k_wo_ffn<<<dim3(MC/32, 1), 256, SM_WOFFN, s0>>>(
        ao, Wo, bo, g1, be1, feats, c1, W1, b1f, hid);
    // FFN down + LN2 + residual(c1) -> c2   (128 blocks)
    k_gemm_ln<32,128,16,32><<<dim3(MC/32, 1), 256, SM_LN, s0>>>(
        hid, W2, b2f, c2, HID, g2, be2, c1, 0);

    cudaStreamWaitEvent(s0, eNear, 0);
    k_scatter<<<NPTS*(DIMF/4)/256, 256, 0, s0>>>(feats, out);
}

// round 10
// speedup vs baseline: 1.0054x; 1.0054x over previous
#include <cuda_runtime.h>
#include <math.h>
#include <stdint.h>

#define NPTS 16384
#define MC   4096
#define DIMF 128
#define NH   4
#define DH   32
#define KNB  32
#define HID  512
#define RAD  0.3f
#define R2L  0.09000902f
#define CAP  512
#define CPB  8

// ---------------- scratch ----------------
__device__ int    g_idxc[MC];
__device__ __align__(16) float g_Qc[MC*DIMF];
__device__ __align__(16) float g_Kp[NPTS*DIMF];
__device__ __align__(16) float g_Vp[NPTS*DIMF];
__device__ int    g_nbr[MC*KNB];
__device__ int    g_cnt[MC];
__device__ int    g_near[NPTS];
__device__ __align__(16) float g_ao[MC*DIMF];
__device__ __align__(16) float g_c1[MC*DIMF];
__device__ __align__(16) float g_hid[MC*HID];
__device__ __align__(16) float g_c2[MC*DIMF];

// ---------------- fused prep: idx convert + top-K + nearest-center ----------
// blocks [0, 512): top-K for 8 centers each (writes g_idxc slice, g_nbr, g_cnt)
// blocks [512, 576): nearest center for 256 points each (writes g_near)
__global__ __launch_bounds__(256) void k_prep(const float* __restrict__ xyz,
                                              const long long* __restrict__ raw) {
    extern __shared__ __align__(16) char sm[];
    __shared__ int s_ok;
    const int tid = threadIdx.x;
    if (tid == 0) {
        int ok = 1;
        for (int i = 0; i < 64; i++) {
            long long v = raw[i];
            if (v < 0 || v >= NPTS) ok = 0;
        }
        s_ok = ok;
    }
    __syncthreads();
    const int* r32 = (const int*)raw;
    const int ok = s_ok;

    if (blockIdx.x < MC/CPB) {
        // ---- top-K role ----
        float (*cd)[CAP] = reinterpret_cast<float(*)[CAP]>(sm);
        int   (*ci)[CAP] = reinterpret_cast<int(*)[CAP]>(sm + CPB*CAP*sizeof(float));
        __shared__ int s_cnt[CPB];
        if (tid < CPB) s_cnt[tid] = 0;
        const int m0 = blockIdx.x * CPB;

        float cx2[CPB], cy2[CPB], cz2[CPB], cc[CPB];
        #pragma unroll
        for (int g = 0; g < CPB; g++) {
            int ic = ok ? (int)raw[m0+g] : r32[m0+g];
            if (tid == g) g_idxc[m0+g] = ic;
            float x = xyz[3*ic], y = xyz[3*ic+1], z = xyz[3*ic+2];
            cx2[g] = -2.f*x; cy2[g] = -2.f*y; cz2[g] = -2.f*z;
            cc[g] = x*x + y*y + z*z;
        }
        __syncthreads();

        for (int n = tid; n < NPTS; n += 256) {
            float x = xyz[3*n], y = xyz[3*n+1], z = xyz[3*n+2];
            float xx = x*x + y*y + z*z;
            float rhs = R2L - xx;
            #pragma unroll
            for (int g = 0; g < CPB; g++) {
                float t = fmaf(cx2[g], x, cc[g]);
                t = fmaf(cy2[g], y, t);
                t = fmaf(cz2[g], z, t);
                if (t < rhs) {
                    float dist = sqrtf(fmaxf(t + xx, 1e-12f));
                    if (dist < RAD) {
                        int q = atomicAdd(&s_cnt[g], 1);
                        if (q < CAP) { cd[g][q] = dist; ci[g][q] = n; }
                    }
                }
            }
        }
        __syncthreads();

        #pragma unroll
        for (int g = 0; g < CPB; g++) {
            int cnt = min(s_cnt[g], CAP);
            int m = m0 + g;
            for (int c = tid; c < cnt; c += 256) {
                float d = cd[g][c]; int i = ci[g][c];
                int rank = 0;
                for (int j = 0; j < cnt; j++) {
                    float dj = cd[g][j];
                    rank += (dj < d) || (dj == d && ci[g][j] < i);
                }
                if (rank < KNB) g_nbr[m*KNB + rank] = i;
            }
            int v = min(cnt, KNB);
            if (tid == 0) g_cnt[m] = v;
            if (tid >= v && tid < KNB) g_nbr[m*KNB + tid] = 0;
        }
    } else {
        // ---- nearest-center role (no atomics; full scan per block) ----
        float4* sc = reinterpret_cast<float4*>(sm);
        const int n = (blockIdx.x - MC/CPB) * 256 + tid;
        const float x = xyz[3*n], y = xyz[3*n+1], z = xyz[3*n+2];
        float best = 3.4e38f; int bi = 0;
        for (int ch = 0; ch < MC/512; ch++) {
            __syncthreads();
            for (int j = tid; j < 512; j += 256) {
                int m = ch*512 + j;
                int ic = ok ? (int)raw[m] : r32[m];
                float a = xyz[3*ic], b = xyz[3*ic+1], c = xyz[3*ic+2];
                sc[j] = make_float4(a, b, c, a*a + b*b + c*c);
            }
            __syncthreads();
            #pragma unroll 8
            for (int j = 0; j < 512; j++) {
                float4 c = sc[j];
                float d = fmaf(-2.f, fmaf(c.x, x, fmaf(c.y, y, c.z*z)), c.w);
                if (d < best) { best = d; bi = ch*512 + j; }
            }
        }
        g_near[n] = bi;
    }
}

// ---------------- TF32 GEMM helpers ----------------
__device__ __forceinline__ uint32_t cvt_tf32(float x) {
    uint32_t r;
    asm("cvt.rna.tf32.f32 %0, %1;" : "=r"(r) : "f"(x));
    return r;
}
__device__ __forceinline__ uint32_t smem_u32(const void* p) {
    return (uint32_t)__cvta_generic_to_shared(p);
}
__device__ __forceinline__ void cp_async16(uint32_t dst, const float* src) {
    asm volatile("cp.async.cg.shared.global [%0], [%1], 16;\n" :: "r"(dst), "l"(src));
}
__device__ __forceinline__ void cp_commit() { asm volatile("cp.async.commit_group;\n"); }
template<int N> __device__ __forceinline__ void cp_wait() {
    asm volatile("cp.async.wait_group %0;\n" :: "n"(N));
}
#define MMA_TF32(acc, a0,a1,a2,a3, b0,b1) \
    asm volatile( \
        "mma.sync.aligned.m16n8k8.row.col.f32.tf32.tf32.f32 " \
        "{%0,%1,%2,%3}, {%4,%5,%6,%7}, {%8,%9}, {%0,%1,%2,%3};\n" \
        : "+f"((acc)[0]), "+f"((acc)[1]), "+f"((acc)[2]), "+f"((acc)[3]) \
        : "r"(a0), "r"(a1), "r"(a2), "r"(a3), "r"(b0), "r"(b1))

// LNMODE: 0 = bias/relu epilogue; 1 = bias -> LayerNorm + residual
// GATHERA: A row r comes from A[idx_center[r]], idx resolved inline from raw
template<int BM, int BN, int WM, int WN, int LNMODE, int GATHERA>
__device__ __forceinline__ void gemm_body(
    const float* __restrict__ A, const float* __restrict__ W,
    const float* __restrict__ bias, float* __restrict__ C,
    int Cin, int Cout, int relu,
    const float* __restrict__ lng, const float* __restrict__ lnb,
    const float* __restrict__ resid, int gatherResid,
    const long long* __restrict__ rawIdx)
{
    constexpr int BK = 16;
    constexpr int LDK = BK + 4;
    constexpr int MT = WM / 16, NT = WN / 8;
    constexpr int WCOLS = BN / WN;
    extern __shared__ __align__(16) char dsm[];
    float (*As)[BM][LDK] = reinterpret_cast<float(*)[BM][LDK]>(dsm);
    float (*Ws)[BN][LDK] = reinterpret_cast<float(*)[BN][LDK]>(dsm + 2*BM*LDK*sizeof(float));

    const int tid = threadIdx.x;
    const int wid = tid >> 5, lane = tid & 31;
    const int wmBase = (wid / WCOLS) * WM;
    const int wnBase = (wid % WCOLS) * WN;
    const int rowBase = blockIdx.x * BM;
    const int colBase = blockIdx.y * BN;
    const int lr = lane >> 2, lc = lane & 3;

    // inline idx_center dtype detection + row resolve (GATHERA: BM*(BK/4)==256)
    __shared__ int s_ok;
    int arow = 0;
    if (GATHERA) {
        if (tid == 0) {
            int ok = 1;
            for (int i = 0; i < 64; i++) {
                long long v = rawIdx[i];
                if (v < 0 || v >= NPTS) ok = 0;
            }
            s_ok = ok;
        }
        __syncthreads();
        int m = rowBase + (tid >> 2);
        arow = s_ok ? (int)rawIdx[m] : ((const int*)rawIdx)[m];
    }

    float acc[MT][NT][4];
    #pragma unroll
    for (int i = 0; i < MT; i++)
        #pragma unroll
        for (int j = 0; j < NT; j++)
            #pragma unroll
            for (int q = 0; q < 4; q++) acc[i][j][q] = 0.f;

    auto copy_tile = [&](int st, int k0) {
        #pragma unroll
        for (int f = tid; f < BM * (BK/4); f += 256) {
            int row = f >> 2, kq = f & 3;
            int ar = GATHERA ? arow : (rowBase + row);
            cp_async16(smem_u32(&As[st][row][kq*4]),
                       A + (size_t)ar*Cin + k0 + kq*4);
        }
        #pragma unroll
        for (int f = tid; f < BN * (BK/4); f += 256) {
            int row = f >> 2, kq = f & 3;
            cp_async16(smem_u32(&Ws[st][row][kq*4]),
                       W + (size_t)(colBase + row)*Cin + k0 + kq*4);
        }
    };

    const int NTILES = Cin / BK;
    copy_tile(0, 0);
    cp_commit();

    for (int t = 0; t < NTILES; t++) {
        const int st = t & 1;
        if (t + 1 < NTILES) { copy_tile(st ^ 1, (t+1)*BK); cp_commit(); cp_wait<1>(); }
        else cp_wait<0>();
        __syncthreads();

        #pragma unroll
        for (int ks = 0; ks < BK/8; ks++) {
            uint32_t bfr[NT][2];
            #pragma unroll
            for (int nt = 0; nt < NT; nt++) {
                int nn = wnBase + nt*8 + lr;
                bfr[nt][0] = cvt_tf32(Ws[st][nn][ks*8 + lc]);
                bfr[nt][1] = cvt_tf32(Ws[st][nn][ks*8 + lc + 4]);
            }
            uint32_t afr[MT][4];
            #pragma unroll
            for (int mt = 0; mt < MT; mt++) {
                int rr = wmBase + mt*16 + lr;
                afr[mt][0] = cvt_tf32(As[st][rr][ks*8 + lc]);
                afr[mt][1] = cvt_tf32(As[st][rr + 8][ks*8 + lc]);
                afr[mt][2] = cvt_tf32(As[st][rr][ks*8 + lc + 4]);
                afr[mt][3] = cvt_tf32(As[st][rr + 8][ks*8 + lc + 4]);
            }
            #pragma unroll
            for (int mt = 0; mt < MT; mt++)
                #pragma unroll
                for (int nt = 0; nt < NT; nt++)
                    MMA_TF32(acc[mt][nt], afr[mt][0], afr[mt][1], afr[mt][2], afr[mt][3],
                             bfr[nt][0], bfr[nt][1]);
        }
        __syncthreads();
    }

    if (LNMODE == 0) {
        #pragma unroll
        for (int mt = 0; mt < MT; mt++) {
            #pragma unroll
            for (int nt = 0; nt < NT; nt++) {
                int row0 = rowBase + wmBase + mt*16 + lr;
                int col  = colBase + wnBase + nt*8 + 2*lc;
                float bx = 0.f, by = 0.f;
                if (bias) { bx = bias[col]; by = bias[col+1]; }
                float2 o0 = make_float2(acc[mt][nt][0] + bx, acc[mt][nt][1] + by);
                float2 o1 = make_float2(acc[mt][nt][2] + bx, acc[mt][nt][3] + by);
                if (relu) {
                    o0.x = fmaxf(o0.x, 0.f); o0.y = fmaxf(o0.y, 0.f);
                    o1.x = fmaxf(o1.x, 0.f); o1.y = fmaxf(o1.y, 0.f);
                }
                *reinterpret_cast<float2*>(C + (size_t)row0*Cout + col) = o0;
                *reinterpret_cast<float2*>(C + (size_t)(row0+8)*Cout + col) = o1;
            }
        }
    } else {
        float (*Cs)[BN + 4] = reinterpret_cast<float(*)[BN + 4]>(dsm);
        #pragma unroll
        for (int mt = 0; mt < MT; mt++) {
            #pragma unroll
            for (int nt = 0; nt < NT; nt++) {
                int r0 = wmBase + mt*16 + lr;
                int col = wnBase + nt*8 + 2*lc;
                float bx = bias[col], by = bias[col+1];
                *reinterpret_cast<float2*>(&Cs[r0][col]) =
                    make_float2(acc[mt][nt][0] + bx, acc[mt][nt][1] + by);
                *reinterpret_cast<float2*>(&Cs[r0 + 8][col]) =
                    make_float2(acc[mt][nt][2] + bx, acc[mt][nt][3] + by);
            }
        }
        __syncthreads();
        #pragma unroll
        for (int r = 0; r < BM/8; r++) {
            int row = wid * (BM/8) + r;
            float4 v = *reinterpret_cast<float4*>(&Cs[row][lane*4]);
            float s = v.x + v.y + v.z + v.w;
            float q = v.x*v.x + v.y*v.y + v.z*v.z + v.w*v.w;
            #pragma unroll
            for (int o = 16; o > 0; o >>= 1) {
                s += __shfl_xor_sync(0xffffffffu, s, o);
                q += __shfl_xor_sync(0xffffffffu, q, o);
            }
            float mu = s * (1.f/DIMF);
            float var = fmaxf(q * (1.f/DIMF) - mu*mu, 0.f);
            float rstd = rsqrtf(var + 1e-5f);
            int grow = rowBase + row;
            int rrow = gatherResid ? g_idxc[grow] : grow;
            float4 gv = *reinterpret_cast<const float4*>(lng + lane*4);
            float4 bv = *reinterpret_cast<const float4*>(lnb + lane*4);
            float4 rv = *reinterpret_cast<const float4*>(resid + (size_t)rrow*DIMF + lane*4);
            float4 o;
            o.x = (v.x - mu) * rstd * gv.x + bv.x + rv.x;
            o.y = (v.y - mu) * rstd * gv.y + bv.y + rv.y;
            o.z = (v.z - mu) * rstd * gv.z + bv.z + rv.z;
            o.w = (v.w - mu) * rstd * gv.w + bv.w + rv.w;
            *reinterpret_cast<float4*>(C + (size_t)grow*DIMF + lane*4) = o;
        }
    }
}

template<int BM, int BN, int WM, int WN>
__global__ __launch_bounds__(256, 3) void k_gemm(
    const float* __restrict__ A, const float* __restrict__ W,
    const float* __restrict__ bias, float* __restrict__ C,
    int Cin, int Cout, int relu)
{
    gemm_body<BM, BN, WM, WN, 0, 0>(A, W, bias, C, Cin, Cout, relu,
                                    nullptr, nullptr, nullptr, 0, nullptr);
}

template<int BM, int BN, int WM, int WN>
__global__ __launch_bounds__(256, 3) void k_gemm_ln(
    const float* __restrict__ A, const float* __restrict__ W,
    const float* __restrict__ bias, float* __restrict__ C, int Cin,
    const float* __restrict__ lng, const float* __restrict__ lnb,
    const float* __restrict__ resid, int gatherResid)
{
    gemm_body<BM, BN, WM, WN, 1, 0>(A, W, bias, C, Cin, DIMF, 0,
                                    lng, lnb, resid, gatherResid, nullptr);
}

// QKV merged: z=0 -> K, z=1 -> V (all points); z=2 -> Q over gathered centers.
// Depends only on harness inputs (idx resolved inline) -> runs parallel to prep.
struct P3 { const float* W[3]; float* C[3]; const long long* raw; };
__global__ __launch_bounds__(256, 3) void k_gemm_qkv(const float* __restrict__ A, P3 p)
{
    int z = blockIdx.z;
    if (z == 2) {
        if (blockIdx.x >= MC/64) return;
        gemm_body<64, 128, 32, 32, 0, 1>(A, p.W[2], nullptr, p.C[2], DIMF, DIMF, 0,
                                         nullptr, nullptr, nullptr, 0, p.raw);
    } else {
        gemm_body<64, 128, 32, 32, 0, 0>(A, p.W[z], nullptr, p.C[z], DIMF, DIMF, 0,
                                         nullptr, nullptr, nullptr, 0, nullptr);
    }
}

// smem byte counts
#define GSM(BM_, BN_) (2 * ((BM_) + (BN_)) * 20 * 4)
static const int SM_64  = GSM(64,128);    // 30720
static const int SM_LN  = GSM(32,128) > (32*(128+4)*4) ? GSM(32,128) : (32*(128+4)*4);
static const int SM_PREP = CPB*CAP*8;     // 32768 (covers both roles)

// ---------------- per-center attention ----------------
__global__ void k_attn() {
    __shared__ float q[DIMF];
    __shared__ float kS[KNB][DIMF + 4];
    __shared__ float vS[KNB][DIMF + 4];
    __shared__ int nbr_s[KNB];
    __shared__ int s_cnt;
    const int m = blockIdx.x, tid = threadIdx.x;
    if (tid < KNB) nbr_s[tid] = g_nbr[m*KNB + tid];
    if (tid == 0) s_cnt = g_cnt[m];
    q[tid] = g_Qc[(size_t)m*DIMF + tid] * 0.17677669529663687f;  // DH^-0.5
    __syncthreads();

    #pragma unroll
    for (int f = tid; f < KNB * (DIMF/4); f += 128) {
        int s = f >> 5, c4 = f & 31;
        size_t off = (size_t)nbr_s[s]*DIMF + c4*4;
        float4 kx = *reinterpret_cast<const float4*>(&g_Kp[off]);
        float4 vx = *reinterpret_cast<const float4*>(&g_Vp[off]);
        *reinterpret_cast<float4*>(&kS[s][c4*4]) = kx;
        *reinterpret_cast<float4*>(&vS[s][c4*4]) = vx;
    }
    __syncthreads();

    const int h = tid >> 5, lane = tid & 31;
    const int cnt = s_cnt;
    float logit = -1e9f;
    if (lane < cnt) {
        float a = 0.f;
        #pragma unroll
        for (int d = 0; d < DH; d++) a += q[h*DH + d] * kS[lane][h*DH + d];
        logit = a;
    }
    float mx = logit;
    #pragma unroll
    for (int o = 16; o > 0; o >>= 1) mx = fmaxf(mx, __shfl_xor_sync(0xffffffffu, mx, o));
    float e = (lane < cnt) ? expf(logit - mx) : 0.f;
    float sm = e;
    #pragma unroll
    for (int o = 16; o > 0; o >>= 1) sm += __shfl_xor_sync(0xffffffffu, sm, o);
    float w = e / sm;

    float acc = 0.f;
    #pragma unroll
    for (int kk = 0; kk < KNB; kk++)
        acc += __shfl_sync(0xffffffffu, w, kk) * vS[kk][h*DH + lane];
    g_ao[(size_t)m*DIMF + lane*NH + h] = acc;
}

// ---------------- final scatter ----------------
__global__ void k_scatter(const float* __restrict__ feats, float* __restrict__ out) {
    int i = blockIdx.x * 256 + threadIdx.x;
    int n = i >> 5, c4 = i & 31;
    int ctr = g_near[n];
    float4 f = *reinterpret_cast<const float4*>(feats + (size_t)n*DIMF + c4*4);
    float4 c = *reinterpret_cast<const float4*>(g_c2 + (size_t)ctr*DIMF + c4*4);
    f.x += c.x; f.y += c.y; f.z += c.z; f.w += c.w;
    *reinterpret_cast<float4*>(out + (size_t)n*DIMF + c4*4) = f;
}

// ---------------- launch (properly forked capture graph) ----------------
extern "C" void kernel_launch(void* const* d_in, const int* in_sizes, int n_in,
                              void* d_out, int out_size) {
    const float* xyz   = (const float*)d_in[0];
    const float* feats = (const float*)d_in[1];
    const long long* idxc = (const long long*)d_in[2];
    const float* Wq = (const float*)d_in[3];
    const float* Wk = (const float*)d_in[4];
    const float* Wv = (const float*)d_in[5];
    const float* Wo = (const float*)d_in[6];
    const float* bo = (const float*)d_in[7];
    const float* g1 = (const float*)d_in[8];
    const float* be1 = (const float*)d_in[9];
    const float* g2 = (const float*)d_in[10];
    const float* be2 = (const float*)d_in[11];
    const float* W1 = (const float*)d_in[12];
    const float* b1f = (const float*)d_in[13];
    const float* W2 = (const float*)d_in[14];
    const float* b2f = (const float*)d_in[15];
    float* out = (float*)d_out;

    float *qc, *kp, *vp, *ao, *c1, *hid, *c2;
    cudaGetSymbolAddress((void**)&qc,  g_Qc);
    cudaGetSymbolAddress((void**)&kp,  g_Kp);
    cudaGetSymbolAddress((void**)&vp,  g_Vp);
    cudaGetSymbolAddress((void**)&ao,  g_ao);
    cudaGetSymbolAddress((void**)&c1,  g_c1);
    cudaGetSymbolAddress((void**)&hid, g_hid);
    cudaGetSymbolAddress((void**)&c2,  g_c2);

    static cudaStream_t s1 = nullptr;
    static cudaEvent_t eFork = nullptr, ePrep = nullptr;
    if (!s1) {
        cudaStreamCreateWithFlags(&s1, cudaStreamNonBlocking);
        cudaEventCreateWithFlags(&eFork, cudaEventDisableTiming);
        cudaEventCreateWithFlags(&ePrep, cudaEventDisableTiming);
    }
    cudaStream_t s0 = 0;

    // fork s1 FROM the capture-origin stream (required for stream capture),
    // then run prep (topk + nearest + idx convert) on s1 parallel to QKV on s0
    cudaEventRecord(eFork, s0);
    cudaStreamWaitEvent(s1, eFork, 0);
    k_prep<<<MC/CPB + NPTS/256, 256, SM_PREP, s1>>>(xyz, idxc);
    cudaEventRecord(ePrep, s1);

    P3 p;
    p.W[0] = Wk; p.W[1] = Wv; p.W[2] = Wq;
    p.C[0] = kp; p.C[1] = vp; p.C[2] = qc;
    p.raw = idxc;
    k_gemm_qkv<<<dim3(NPTS/64, 1, 3), 256, SM_64, s0>>>(feats, p);

    cudaStreamWaitEvent(s0, ePrep, 0);
    k_attn<<<MC, 128, 0, s0>>>();

    // Wo GEMM + LN1 + residual(feats gathered by idxc) -> c1   (128 blocks)
    k_gemm_ln<32,128,16,32><<<dim3(MC/32, 1), 256, SM_LN, s0>>>(
        ao, Wo, bo, c1, DIMF, g1, be1, feats, 1);
    // FFN up (relu)   (256 blocks)
    k_gemm<64,128,32,32><<<dim3(MC/64, HID/128), 256, SM_64, s0>>>(
        c1, W1, b1f, hid, DIMF, HID, 1);
    // FFN down + LN2 + residual(c1) -> c2   (128 blocks)
    k_gemm_ln<32,128,16,32><<<dim3(MC/32, 1), 256, SM_LN, s0>>>(
        hid, W2, b2f, c2, HID, g2, be2, c1, 0);

    k_scatter<<<NPTS*(DIMF/4)/256, 256, 0, s0>>>(feats, out);
}

// round 12
// speedup vs baseline: 1.0076x; 1.0023x over previous
#include <cuda_runtime.h>
#include <math.h>
#include <stdint.h>

#define NPTS 16384
#define MC   4096
#define DIMF 128
#define NH   4
#define DH   32
#define KNB  32
#define HID  512
#define RAD  0.3f
#define R2L  0.09000902f
#define CAP  512
#define CPB  8

// ---------------- scratch ----------------
__device__ int    g_idxc[MC];
__device__ __align__(16) float g_Qc[MC*DIMF];
__device__ __align__(16) float g_Kp[NPTS*DIMF];
__device__ __align__(16) float g_Vp[NPTS*DIMF];
__device__ int    g_nbr[MC*KNB];
__device__ int    g_cnt[MC];
__device__ int    g_near[NPTS];
__device__ __align__(16) float g_ao[MC*DIMF];
__device__ __align__(16) float g_c1[MC*DIMF];
__device__ __align__(16) float g_hid[MC*HID];
__device__ __align__(16) float g_c2[MC*DIMF];

// ---------------- fused prep: idx convert + top-K + nearest-center ----------
__global__ __launch_bounds__(256) void k_prep(const float* __restrict__ xyz,
                                              const long long* __restrict__ raw) {
    extern __shared__ __align__(16) char sm[];
    __shared__ int s_ok;
    const int tid = threadIdx.x;
    if (tid == 0) {
        int ok = 1;
        for (int i = 0; i < 64; i++) {
            long long v = raw[i];
            if (v < 0 || v >= NPTS) ok = 0;
        }
        s_ok = ok;
    }
    __syncthreads();
    const int* r32 = (const int*)raw;
    const int ok = s_ok;

    if (blockIdx.x < MC/CPB) {
        float (*cd)[CAP] = reinterpret_cast<float(*)[CAP]>(sm);
        int   (*ci)[CAP] = reinterpret_cast<int(*)[CAP]>(sm + CPB*CAP*sizeof(float));
        __shared__ int s_cnt[CPB];
        if (tid < CPB) s_cnt[tid] = 0;
        const int m0 = blockIdx.x * CPB;

        float cx2[CPB], cy2[CPB], cz2[CPB], cc[CPB];
        #pragma unroll
        for (int g = 0; g < CPB; g++) {
            int ic = ok ? (int)raw[m0+g] : r32[m0+g];
            if (tid == g) g_idxc[m0+g] = ic;
            float x = xyz[3*ic], y = xyz[3*ic+1], z = xyz[3*ic+2];
            cx2[g] = -2.f*x; cy2[g] = -2.f*y; cz2[g] = -2.f*z;
            cc[g] = x*x + y*y + z*z;
        }
        __syncthreads();

        for (int n = tid; n < NPTS; n += 256) {
            float x = xyz[3*n], y = xyz[3*n+1], z = xyz[3*n+2];
            float xx = x*x + y*y + z*z;
            float rhs = R2L - xx;
            #pragma unroll
            for (int g = 0; g < CPB; g++) {
                float t = fmaf(cx2[g], x, cc[g]);
                t = fmaf(cy2[g], y, t);
                t = fmaf(cz2[g], z, t);
                if (t < rhs) {
                    float dist = sqrtf(fmaxf(t + xx, 1e-12f));
                    if (dist < RAD) {
                        int q = atomicAdd(&s_cnt[g], 1);
                        if (q < CAP) { cd[g][q] = dist; ci[g][q] = n; }
                    }
                }
            }
        }
        __syncthreads();

        #pragma unroll
        for (int g = 0; g < CPB; g++) {
            int cnt = min(s_cnt[g], CAP);
            int m = m0 + g;
            for (int c = tid; c < cnt; c += 256) {
                float d = cd[g][c]; int i = ci[g][c];
                int rank = 0;
                for (int j = 0; j < cnt; j++) {
                    float dj = cd[g][j];
                    rank += (dj < d) || (dj == d && ci[g][j] < i);
                }
                if (rank < KNB) g_nbr[m*KNB + rank] = i;
            }
            int v = min(cnt, KNB);
            if (tid == 0) g_cnt[m] = v;
            if (tid >= v && tid < KNB) g_nbr[m*KNB + tid] = 0;
        }
    } else {
        float4* sc = reinterpret_cast<float4*>(sm);
        const int n = (blockIdx.x - MC/CPB) * 256 + tid;
        const float x = xyz[3*n], y = xyz[3*n+1], z = xyz[3*n+2];
        float best = 3.4e38f; int bi = 0;
        for (int ch = 0; ch < MC/512; ch++) {
            __syncthreads();
            for (int j = tid; j < 512; j += 256) {
                int m = ch*512 + j;
                int ic = ok ? (int)raw[m] : r32[m];
                float a = xyz[3*ic], b = xyz[3*ic+1], c = xyz[3*ic+2];
                sc[j] = make_float4(a, b, c, a*a + b*b + c*c);
            }
            __syncthreads();
            #pragma unroll 8
            for (int j = 0; j < 512; j++) {
                float4 c = sc[j];
                float d = fmaf(-2.f, fmaf(c.x, x, fmaf(c.y, y, c.z*z)), c.w);
                if (d < best) { best = d; bi = ch*512 + j; }
            }
        }
        g_near[n] = bi;
    }
}

// ---------------- TF32 GEMM helpers ----------------
__device__ __forceinline__ uint32_t cvt_tf32(float x) {
    uint32_t r;
    asm("cvt.rna.tf32.f32 %0, %1;" : "=r"(r) : "f"(x));
    return r;
}
__device__ __forceinline__ uint32_t smem_u32(const void* p) {
    return (uint32_t)__cvta_generic_to_shared(p);
}
__device__ __forceinline__ void cp_async16(uint32_t dst, const float* src) {
    asm volatile("cp.async.cg.shared.global [%0], [%1], 16;\n" :: "r"(dst), "l"(src));
}
__device__ __forceinline__ void cp_commit() { asm volatile("cp.async.commit_group;\n"); }
template<int N> __device__ __forceinline__ void cp_wait() {
    asm volatile("cp.async.wait_group %0;\n" :: "n"(N));
}
#define MMA_TF32(acc, a0,a1,a2,a3, b0,b1) \
    asm volatile( \
        "mma.sync.aligned.m16n8k8.row.col.f32.tf32.tf32.f32 " \
        "{%0,%1,%2,%3}, {%4,%5,%6,%7}, {%8,%9}, {%0,%1,%2,%3};\n" \
        : "+f"((acc)[0]), "+f"((acc)[1]), "+f"((acc)[2]), "+f"((acc)[3]) \
        : "r"(a0), "r"(a1), "r"(a2), "r"(a3), "r"(b0), "r"(b1))

// LNMODE: 0 = bias/relu epilogue; 1 = bias -> LayerNorm + residual
// GATHERA: A row r comes from A[idx_center[r]] — indices staged in s_rows[BM]
// (valid for ANY BM/BK combination; fixes the round-11 per-thread-index bug)
template<int BM, int BN, int WM, int WN, int BK, int LNMODE, int GATHERA>
__device__ __forceinline__ void gemm_body(
    const float* __restrict__ A, const float* __restrict__ W,
    const float* __restrict__ bias, float* __restrict__ C,
    int Cin, int Cout, int relu,
    const float* __restrict__ lng, const float* __restrict__ lnb,
    const float* __restrict__ resid, int gatherResid,
    const long long* __restrict__ rawIdx)
{
    constexpr int LDK = BK + 4;
    constexpr int KQ = BK / 4;
    constexpr int MT = WM / 16, NT = WN / 8;
    constexpr int WCOLS = BN / WN;
    extern __shared__ __align__(16) char dsm[];
    float (*As)[BM][LDK] = reinterpret_cast<float(*)[BM][LDK]>(dsm);
    float (*Ws)[BN][LDK] = reinterpret_cast<float(*)[BN][LDK]>(dsm + 2*BM*LDK*sizeof(float));

    const int tid = threadIdx.x;
    const int wid = tid >> 5, lane = tid & 31;
    const int wmBase = (wid / WCOLS) * WM;
    const int wnBase = (wid % WCOLS) * WN;
    const int rowBase = blockIdx.x * BM;
    const int colBase = blockIdx.y * BN;
    const int lr = lane >> 2, lc = lane & 3;

    __shared__ int s_rows[BM];
    if (GATHERA) {
        __shared__ int s_ok;
        if (tid == 0) {
            int ok = 1;
            for (int i = 0; i < 64; i++) {
                long long v = rawIdx[i];
                if (v < 0 || v >= NPTS) ok = 0;
            }
            s_ok = ok;
        }
        __syncthreads();
        for (int i = tid; i < BM; i += 256)
            s_rows[i] = s_ok ? (int)rawIdx[rowBase + i]
                             : ((const int*)rawIdx)[rowBase + i];
        __syncthreads();
    }

    float acc[MT][NT][4];
    #pragma unroll
    for (int i = 0; i < MT; i++)
        #pragma unroll
        for (int j = 0; j < NT; j++)
            #pragma unroll
            for (int q = 0; q < 4; q++) acc[i][j][q] = 0.f;

    auto copy_tile = [&](int st, int k0) {
        #pragma unroll
        for (int f = tid; f < BM * KQ; f += 256) {
            int row = f / KQ, kq = f % KQ;
            int ar = GATHERA ? s_rows[row] : (rowBase + row);
            cp_async16(smem_u32(&As[st][row][kq*4]),
                       A + (size_t)ar*Cin + k0 + kq*4);
        }
        #pragma unroll
        for (int f = tid; f < BN * KQ; f += 256) {
            int row = f / KQ, kq = f % KQ;
            cp_async16(smem_u32(&Ws[st][row][kq*4]),
                       W + (size_t)(colBase + row)*Cin + k0 + kq*4);
        }
    };

    const int NTILES = Cin / BK;
    copy_tile(0, 0);
    cp_commit();

    for (int t = 0; t < NTILES; t++) {
        const int st = t & 1;
        if (t + 1 < NTILES) { copy_tile(st ^ 1, (t+1)*BK); cp_commit(); cp_wait<1>(); }
        else cp_wait<0>();
        __syncthreads();

        #pragma unroll
        for (int ks = 0; ks < BK/8; ks++) {
            uint32_t bfr[NT][2];
            #pragma unroll
            for (int nt = 0; nt < NT; nt++) {
                int nn = wnBase + nt*8 + lr;
                bfr[nt][0] = cvt_tf32(Ws[st][nn][ks*8 + lc]);
                bfr[nt][1] = cvt_tf32(Ws[st][nn][ks*8 + lc + 4]);
            }
            uint32_t afr[MT][4];
            #pragma unroll
            for (int mt = 0; mt < MT; mt++) {
                int rr = wmBase + mt*16 + lr;
                afr[mt][0] = cvt_tf32(As[st][rr][ks*8 + lc]);
                afr[mt][1] = cvt_tf32(As[st][rr + 8][ks*8 + lc]);
                afr[mt][2] = cvt_tf32(As[st][rr][ks*8 + lc + 4]);
                afr[mt][3] = cvt_tf32(As[st][rr + 8][ks*8 + lc + 4]);
            }
            #pragma unroll
            for (int mt = 0; mt < MT; mt++)
                #pragma unroll
                for (int nt = 0; nt < NT; nt++)
                    MMA_TF32(acc[mt][nt], afr[mt][0], afr[mt][1], afr[mt][2], afr[mt][3],
                             bfr[nt][0], bfr[nt][1]);
        }
        __syncthreads();
    }

    if (LNMODE == 0) {
        #pragma unroll
        for (int mt = 0; mt < MT; mt++) {
            #pragma unroll
            for (int nt = 0; nt < NT; nt++) {
                int row0 = rowBase + wmBase + mt*16 + lr;
                int col  = colBase + wnBase + nt*8 + 2*lc;
                float bx = 0.f, by = 0.f;
                if (bias) { bx = bias[col]; by = bias[col+1]; }
                float2 o0 = make_float2(acc[mt][nt][0] + bx, acc[mt][nt][1] + by);
                float2 o1 = make_float2(acc[mt][nt][2] + bx, acc[mt][nt][3] + by);
                if (relu) {
                    o0.x = fmaxf(o0.x, 0.f); o0.y = fmaxf(o0.y, 0.f);
                    o1.x = fmaxf(o1.x, 0.f); o1.y = fmaxf(o1.y, 0.f);
                }
                *reinterpret_cast<float2*>(C + (size_t)row0*Cout + col) = o0;
                *reinterpret_cast<float2*>(C + (size_t)(row0+8)*Cout + col) = o1;
            }
        }
    } else {
        float (*Cs)[BN + 4] = reinterpret_cast<float(*)[BN + 4]>(dsm);
        #pragma unroll
        for (int mt = 0; mt < MT; mt++) {
            #pragma unroll
            for (int nt = 0; nt < NT; nt++) {
                int r0 = wmBase + mt*16 + lr;
                int col = wnBase + nt*8 + 2*lc;
                float bx = bias[col], by = bias[col+1];
                *reinterpret_cast<float2*>(&Cs[r0][col]) =
                    make_float2(acc[mt][nt][0] + bx, acc[mt][nt][1] + by);
                *reinterpret_cast<float2*>(&Cs[r0 + 8][col]) =
                    make_float2(acc[mt][nt][2] + bx, acc[mt][nt][3] + by);
            }
        }
        __syncthreads();
        #pragma unroll
        for (int r = 0; r < BM/8; r++) {
            int row = wid * (BM/8) + r;
            float4 v = *reinterpret_cast<float4*>(&Cs[row][lane*4]);
            float s = v.x + v.y + v.z + v.w;
            float q = v.x*v.x + v.y*v.y + v.z*v.z + v.w*v.w;
            #pragma unroll
            for (int o = 16; o > 0; o >>= 1) {
                s += __shfl_xor_sync(0xffffffffu, s, o);
                q += __shfl_xor_sync(0xffffffffu, q, o);
            }
            float mu = s * (1.f/DIMF);
            float var = fmaxf(q * (1.f/DIMF) - mu*mu, 0.f);
            float rstd = rsqrtf(var + 1e-5f);
            int grow = rowBase + row;
            int rrow = gatherResid ? g_idxc[grow] : grow;
            float4 gv = *reinterpret_cast<const float4*>(lng + lane*4);
            float4 bv = *reinterpret_cast<const float4*>(lnb + lane*4);
            float4 rv = *reinterpret_cast<const float4*>(resid + (size_t)rrow*DIMF + lane*4);
            float4 o;
            o.x = (v.x - mu) * rstd * gv.x + bv.x + rv.x;
            o.y = (v.y - mu) * rstd * gv.y + bv.y + rv.y;
            o.z = (v.z - mu) * rstd * gv.z + bv.z + rv.z;
            o.w = (v.w - mu) * rstd * gv.w + bv.w + rv.w;
            *reinterpret_cast<float4*>(C + (size_t)grow*DIMF + lane*4) = o;
        }
    }
}

template<int BM, int BN, int WM, int WN, int BK>
__global__ __launch_bounds__(256, 3) void k_gemm(
    const float* __restrict__ A, const float* __restrict__ W,
    const float* __restrict__ bias, float* __restrict__ C,
    int Cin, int Cout, int relu)
{
    gemm_body<BM, BN, WM, WN, BK, 0, 0>(A, W, bias, C, Cin, Cout, relu,
                                        nullptr, nullptr, nullptr, 0, nullptr);
}

template<int BM, int BN, int WM, int WN, int BK>
__global__ __launch_bounds__(256, 3) void k_gemm_ln(
    const float* __restrict__ A, const float* __restrict__ W,
    const float* __restrict__ bias, float* __restrict__ C, int Cin,
    const float* __restrict__ lng, const float* __restrict__ lnb,
    const float* __restrict__ resid, int gatherResid)
{
    gemm_body<BM, BN, WM, WN, BK, 1, 0>(A, W, bias, C, Cin, DIMF, 0,
                                        lng, lnb, resid, gatherResid, nullptr);
}

// QKV merged: z=0 -> K, z=1 -> V (all points); z=2 -> Q over gathered centers.
struct P3 { const float* W[3]; float* C[3]; const long long* raw; };
__global__ __launch_bounds__(256, 3) void k_gemm_qkv(const float* __restrict__ A, P3 p)
{
    int z = blockIdx.z;
    if (z == 2) {
        if (blockIdx.x >= MC/64) return;
        gemm_body<64, 128, 32, 32, 32, 0, 1>(A, p.W[2], nullptr, p.C[2], DIMF, DIMF, 0,
                                             nullptr, nullptr, nullptr, 0, p.raw);
    } else {
        gemm_body<64, 128, 32, 32, 32, 0, 0>(A, p.W[z], nullptr, p.C[z], DIMF, DIMF, 0,
                                             nullptr, nullptr, nullptr, 0, nullptr);
    }
}

// smem byte counts (BK=32 pipeline, 2 stages, LDK=36)
#define GSM32(BM_, BN_) (2 * ((BM_) + (BN_)) * 36 * 4)
static const int SM_QKV = GSM32(64,128);   // 55296 (>48KB -> opt-in)
static const int SM_W1  = GSM32(64,128);   // 55296
static const int SM_LN  = GSM32(16,128) > (16*(128+4)*4) ? GSM32(16,128) : (16*(128+4)*4); // 41472
static const int SM_PREP = CPB*CAP*8;      // 32768

// ---------------- per-center attention ----------------
__global__ void k_attn() {
    __shared__ float q[DIMF];
    __shared__ float kS[KNB][DIMF + 4];
    __shared__ float vS[KNB][DIMF + 4];
    __shared__ int nbr_s[KNB];
    __shared__ int s_cnt;
    const int m = blockIdx.x, tid = threadIdx.x;
    if (tid < KNB) nbr_s[tid] = g_nbr[m*KNB + tid];
    if (tid == 0) s_cnt = g_cnt[m];
    q[tid] = g_Qc[(size_t)m*DIMF + tid] * 0.17677669529663687f;  // DH^-0.5
    __syncthreads();

    #pragma unroll
    for (int f = tid; f < KNB * (DIMF/4); f += 128) {
        int s = f >> 5, c4 = f & 31;
        size_t off = (size_t)nbr_s[s]*DIMF + c4*4;
        float4 kx = *reinterpret_cast<const float4*>(&g_Kp[off]);
        float4 vx = *reinterpret_cast<const float4*>(&g_Vp[off]);
        *reinterpret_cast<float4*>(&kS[s][c4*4]) = kx;
        *reinterpret_cast<float4*>(&vS[s][c4*4]) = vx;
    }
    __syncthreads();

    const int h = tid >> 5, lane = tid & 31;
    const int cnt = s_cnt;
    float logit = -1e9f;
    if (lane < cnt) {
        float a = 0.f;
        #pragma unroll
        for (int d = 0; d < DH; d++) a += q[h*DH + d] * kS[lane][h*DH + d];
        logit = a;
    }
    float mx = logit;
    #pragma unroll
    for (int o = 16; o > 0; o >>= 1) mx = fmaxf(mx, __shfl_xor_sync(0xffffffffu, mx, o));
    float e = (lane < cnt) ? expf(logit - mx) : 0.f;
    float sm = e;
    #pragma unroll
    for (int o = 16; o > 0; o >>= 1) sm += __shfl_xor_sync(0xffffffffu, sm, o);
    float w = e / sm;

    float acc = 0.f;
    #pragma unroll
    for (int kk = 0; kk < KNB; kk++)
        acc += __shfl_sync(0xffffffffu, w, kk) * vS[kk][h*DH + lane];
    g_ao[(size_t)m*DIMF + lane*NH + h] = acc;
}

// ---------------- final scatter ----------------
__global__ void k_scatter(const float* __restrict__ feats, float* __restrict__ out) {
    int i = blockIdx.x * 256 + threadIdx.x;
    int n = i >> 5, c4 = i & 31;
    int ctr = g_near[n];
    float4 f = *reinterpret_cast<const float4*>(feats + (size_t)n*DIMF + c4*4);
    float4 c = *reinterpret_cast<const float4*>(g_c2 + (size_t)ctr*DIMF + c4*4);
    f.x += c.x; f.y += c.y; f.z += c.z; f.w += c.w;
    *reinterpret_cast<float4*>(out + (size_t)n*DIMF + c4*4) = f;
}

// ---------------- launch ----------------
extern "C" void kernel_launch(void* const* d_in, const int* in_sizes, int n_in,
                              void* d_out, int out_size) {
    const float* xyz   = (const float*)d_in[0];
    const float* feats = (const float*)d_in[1];
    const long long* idxc = (const long long*)d_in[2];
    const float* Wq = (const float*)d_in[3];
    const float* Wk = (const float*)d_in[4];
    const float* Wv = (const float*)d_in[5];
    const float* Wo = (const float*)d_in[6];
    const float* bo = (const float*)d_in[7];
    const float* g1 = (const float*)d_in[8];
    const float* be1 = (const float*)d_in[9];
    const float* g2 = (const float*)d_in[10];
    const float* be2 = (const float*)d_in[11];
    const float* W1 = (const float*)d_in[12];
    const float* b1f = (const float*)d_in[13];
    const float* W2 = (const float*)d_in[14];
    const float* b2f = (const float*)d_in[15];
    float* out = (float*)d_out;

    float *qc, *kp, *vp, *ao, *c1, *hid, *c2;
    cudaGetSymbolAddress((void**)&qc,  g_Qc);
    cudaGetSymbolAddress((void**)&kp,  g_Kp);
    cudaGetSymbolAddress((void**)&vp,  g_Vp);
    cudaGetSymbolAddress((void**)&ao,  g_ao);
    cudaGetSymbolAddress((void**)&c1,  g_c1);
    cudaGetSymbolAddress((void**)&hid, g_hid);
    cudaGetSymbolAddress((void**)&c2,  g_c2);

    static cudaStream_t s1 = nullptr;
    static cudaEvent_t eFork = nullptr, ePrep = nullptr;
    if (!s1) {
        cudaStreamCreateWithFlags(&s1, cudaStreamNonBlocking);
        cudaEventCreateWithFlags(&eFork, cudaEventDisableTiming);
        cudaEventCreateWithFlags(&ePrep, cudaEventDisableTiming);
        cudaFuncSetAttribute(k_gemm_qkv,
            cudaFuncAttributeMaxDynamicSharedMemorySize, SM_QKV);
        cudaFuncSetAttribute(k_gemm<64,128,32,32,32>,
            cudaFuncAttributeMaxDynamicSharedMemorySize, SM_W1);
        cudaFuncSetAttribute(k_gemm_ln<16,128,16,16,32>,
            cudaFuncAttributeMaxDynamicSharedMemorySize, SM_LN);
    }
    cudaStream_t s0 = 0;

    // fork s1 from capture-origin stream, run prep parallel to QKV
    cudaEventRecord(eFork, s0);
    cudaStreamWaitEvent(s1, eFork, 0);
    k_prep<<<MC/CPB + NPTS/256, 256, SM_PREP, s1>>>(xyz, idxc);
    cudaEventRecord(ePrep, s1);

    P3 p;
    p.W[0] = Wk; p.W[1] = Wv; p.W[2] = Wq;
    p.C[0] = kp; p.C[1] = vp; p.C[2] = qc;
    p.raw = idxc;
    k_gemm_qkv<<<dim3(NPTS/64, 1, 3), 256, SM_QKV, s0>>>(feats, p);

    cudaStreamWaitEvent(s0, ePrep, 0);
    k_attn<<<MC, 128, 0, s0>>>();

    // Wo GEMM + LN1 + residual(feats gathered) -> c1   (256 blocks)
    k_gemm_ln<16,128,16,16,32><<<dim3(MC/16, 1), 256, SM_LN, s0>>>(
        ao, Wo, bo, c1, DIMF, g1, be1, feats, 1);
    // FFN up (relu)   (256 blocks)
    k_gemm<64,128,32,32,32><<<dim3(MC/64, HID/128), 256, SM_W1, s0>>>(
        c1, W1, b1f, hid, DIMF, HID, 1);
    // FFN down + LN2 + residual(c1) -> c2   (256 blocks)
    k_gemm_ln<16,128,16,16,32><<<dim3(MC/16, 1), 256, SM_LN, s0>>>(
        hid, W2, b2f, c2, HID, g2, be2, c1, 0);

    k_scatter<<<NPTS*(DIMF/4)/256, 256, 0, s0>>>(feats, out);
}

// round 13
// speedup vs baseline: 1.0211x; 1.0134x over previous
#include <cuda_runtime.h>
#include <math.h>
#include <stdint.h>

#define NPTS 16384
#define MC   4096
#define DIMF 128
#define NH   4
#define DH   32
#define KNB  32
#define HID  512
#define RAD  0.3f
#define R2L  0.09000902f
#define CAP  512
#define CPB  8

// ---------------- scratch ----------------
__device__ int    g_idxc[MC];
__device__ __align__(16) float g_Qc[MC*DIMF];
__device__ __align__(16) float g_Kp[NPTS*DIMF];
__device__ __align__(16) float g_Vp[NPTS*DIMF];
__device__ int    g_nbr[MC*KNB];
__device__ int    g_cnt[MC];
__device__ int    g_near[NPTS];
__device__ __align__(16) float g_ao[MC*DIMF];
__device__ __align__(16) float g_c1[MC*DIMF];
__device__ __align__(16) float g_hid[MC*HID];
__device__ __align__(16) float g_c2[MC*DIMF];

// ---------------- fused prep: idx convert + top-K + nearest-center ----------
__global__ __launch_bounds__(256) void k_prep(const float* __restrict__ xyz,
                                              const long long* __restrict__ raw) {
    extern __shared__ __align__(16) char sm[];
    __shared__ int s_ok;
    const int tid = threadIdx.x;
    if (tid == 0) {
        int ok = 1;
        for (int i = 0; i < 64; i++) {
            long long v = raw[i];
            if (v < 0 || v >= NPTS) ok = 0;
        }
        s_ok = ok;
    }
    __syncthreads();
    const int* r32 = (const int*)raw;
    const int ok = s_ok;

    if (blockIdx.x < MC/CPB) {
        float (*cd)[CAP] = reinterpret_cast<float(*)[CAP]>(sm);
        int   (*ci)[CAP] = reinterpret_cast<int(*)[CAP]>(sm + CPB*CAP*sizeof(float));
        __shared__ int s_cnt[CPB];
        if (tid < CPB) s_cnt[tid] = 0;
        const int m0 = blockIdx.x * CPB;

        float cx2[CPB], cy2[CPB], cz2[CPB], cc[CPB];
        #pragma unroll
        for (int g = 0; g < CPB; g++) {
            int ic = ok ? (int)raw[m0+g] : r32[m0+g];
            if (tid == g) g_idxc[m0+g] = ic;
            float x = xyz[3*ic], y = xyz[3*ic+1], z = xyz[3*ic+2];
            cx2[g] = -2.f*x; cy2[g] = -2.f*y; cz2[g] = -2.f*z;
            cc[g] = x*x + y*y + z*z;
        }
        __syncthreads();

        for (int n = tid; n < NPTS; n += 256) {
            float x = xyz[3*n], y = xyz[3*n+1], z = xyz[3*n+2];
            float xx = x*x + y*y + z*z;
            float rhs = R2L - xx;
            #pragma unroll
            for (int g = 0; g < CPB; g++) {
                float t = fmaf(cx2[g], x, cc[g]);
                t = fmaf(cy2[g], y, t);
                t = fmaf(cz2[g], z, t);
                if (t < rhs) {
                    float dist = sqrtf(fmaxf(t + xx, 1e-12f));
                    if (dist < RAD) {
                        int q = atomicAdd(&s_cnt[g], 1);
                        if (q < CAP) { cd[g][q] = dist; ci[g][q] = n; }
                    }
                }
            }
        }
        __syncthreads();

        #pragma unroll
        for (int g = 0; g < CPB; g++) {
            int cnt = min(s_cnt[g], CAP);
            int m = m0 + g;
            for (int c = tid; c < cnt; c += 256) {
                float d = cd[g][c]; int i = ci[g][c];
                int rank = 0;
                for (int j = 0; j < cnt; j++) {
                    float dj = cd[g][j];
                    rank += (dj < d) || (dj == d && ci[g][j] < i);
                }
                if (rank < KNB) g_nbr[m*KNB + rank] = i;
            }
            int v = min(cnt, KNB);
            if (tid == 0) g_cnt[m] = v;
            if (tid >= v && tid < KNB) g_nbr[m*KNB + tid] = 0;
        }
    } else {
        float4* sc = reinterpret_cast<float4*>(sm);
        const int n = (blockIdx.x - MC/CPB) * 256 + tid;
        const float x = xyz[3*n], y = xyz[3*n+1], z = xyz[3*n+2];
        float best = 3.4e38f; int bi = 0;
        for (int ch = 0; ch < MC/512; ch++) {
            __syncthreads();
            for (int j = tid; j < 512; j += 256) {
                int m = ch*512 + j;
                int ic = ok ? (int)raw[m] : r32[m];
                float a = xyz[3*ic], b = xyz[3*ic+1], c = xyz[3*ic+2];
                sc[j] = make_float4(a, b, c, a*a + b*b + c*c);
            }
            __syncthreads();
            #pragma unroll 8
            for (int j = 0; j < 512; j++) {
                float4 c = sc[j];
                float d = fmaf(-2.f, fmaf(c.x, x, fmaf(c.y, y, c.z*z)), c.w);
                if (d < best) { best = d; bi = ch*512 + j; }
            }
        }
        g_near[n] = bi;
    }
}

// ---------------- TF32 GEMM helpers ----------------
__device__ __forceinline__ uint32_t cvt_tf32(float x) {
    uint32_t r;
    asm("cvt.rna.tf32.f32 %0, %1;" : "=r"(r) : "f"(x));
    return r;
}
__device__ __forceinline__ uint32_t smem_u32(const void* p) {
    return (uint32_t)__cvta_generic_to_shared(p);
}
__device__ __forceinline__ void cp_async16(uint32_t dst, const float* src) {
    asm volatile("cp.async.cg.shared.global [%0], [%1], 16;\n" :: "r"(dst), "l"(src));
}
__device__ __forceinline__ void cp_commit() { asm volatile("cp.async.commit_group;\n"); }
template<int N> __device__ __forceinline__ void cp_wait() {
    asm volatile("cp.async.wait_group %0;\n" :: "n"(N));
}
#define MMA_TF32(acc, a0,a1,a2,a3, b0,b1) \
    asm volatile( \
        "mma.sync.aligned.m16n8k8.row.col.f32.tf32.tf32.f32 " \
        "{%0,%1,%2,%3}, {%4,%5,%6,%7}, {%8,%9}, {%0,%1,%2,%3};\n" \
        : "+f"((acc)[0]), "+f"((acc)[1]), "+f"((acc)[2]), "+f"((acc)[3]) \
        : "r"(a0), "r"(a1), "r"(a2), "r"(a3), "r"(b0), "r"(b1))

// LNMODE: 0 = bias/relu epilogue; 1 = bias -> LayerNorm + residual
// GATHERA: A row r comes from A[idx_center[r]] — indices staged in s_rows[BM]
// NSTAGE: cp.async pipeline depth (2 or 3)
template<int BM, int BN, int WM, int WN, int BK, int NSTAGE, int LNMODE, int GATHERA>
__device__ __forceinline__ void gemm_body(
    const float* __restrict__ A, const float* __restrict__ W,
    const float* __restrict__ bias, float* __restrict__ C,
    int Cin, int Cout, int relu,
    const float* __restrict__ lng, const float* __restrict__ lnb,
    const float* __restrict__ resid, int gatherResid,
    const long long* __restrict__ rawIdx)
{
    constexpr int LDK = BK + 4;
    constexpr int KQ = BK / 4;
    constexpr int MT = WM / 16, NT = WN / 8;
    constexpr int WCOLS = BN / WN;
    extern __shared__ __align__(16) char dsm[];
    float (*As)[BM][LDK] = reinterpret_cast<float(*)[BM][LDK]>(dsm);
    float (*Ws)[BN][LDK] = reinterpret_cast<float(*)[BN][LDK]>(dsm + NSTAGE*BM*LDK*sizeof(float));

    const int tid = threadIdx.x;
    const int wid = tid >> 5, lane = tid & 31;
    const int wmBase = (wid / WCOLS) * WM;
    const int wnBase = (wid % WCOLS) * WN;
    const int rowBase = blockIdx.x * BM;
    const int colBase = blockIdx.y * BN;
    const int lr = lane >> 2, lc = lane & 3;

    __shared__ int s_rows[BM];
    if (GATHERA) {
        __shared__ int s_ok;
        if (tid == 0) {
            int ok = 1;
            for (int i = 0; i < 64; i++) {
                long long v = rawIdx[i];
                if (v < 0 || v >= NPTS) ok = 0;
            }
            s_ok = ok;
        }
        __syncthreads();
        for (int i = tid; i < BM; i += 256)
            s_rows[i] = s_ok ? (int)rawIdx[rowBase + i]
                             : ((const int*)rawIdx)[rowBase + i];
        __syncthreads();
    }

    float acc[MT][NT][4];
    #pragma unroll
    for (int i = 0; i < MT; i++)
        #pragma unroll
        for (int j = 0; j < NT; j++)
            #pragma unroll
            for (int q = 0; q < 4; q++) acc[i][j][q] = 0.f;

    auto copy_tile = [&](int st, int k0) {
        #pragma unroll
        for (int f = tid; f < BM * KQ; f += 256) {
            int row = f / KQ, kq = f % KQ;
            int ar = GATHERA ? s_rows[row] : (rowBase + row);
            cp_async16(smem_u32(&As[st][row][kq*4]),
                       A + (size_t)ar*Cin + k0 + kq*4);
        }
        #pragma unroll
        for (int f = tid; f < BN * KQ; f += 256) {
            int row = f / KQ, kq = f % KQ;
            cp_async16(smem_u32(&Ws[st][row][kq*4]),
                       W + (size_t)(colBase + row)*Cin + k0 + kq*4);
        }
    };

    const int NTILES = Cin / BK;
    #pragma unroll
    for (int i = 0; i < NSTAGE-1; i++) {
        if (i < NTILES) { copy_tile(i, i*BK); cp_commit(); }
    }

    for (int t = 0; t < NTILES; t++) {
        const int st = t % NSTAGE;
        if (t + NSTAGE-1 < NTILES) {
            copy_tile((t + NSTAGE-1) % NSTAGE, (t + NSTAGE-1)*BK);
            cp_commit();
            cp_wait<NSTAGE-2>();
        } else {
            cp_wait<0>();
        }
        __syncthreads();

        #pragma unroll
        for (int ks = 0; ks < BK/8; ks++) {
            uint32_t bfr[NT][2];
            #pragma unroll
            for (int nt = 0; nt < NT; nt++) {
                int nn = wnBase + nt*8 + lr;
                bfr[nt][0] = cvt_tf32(Ws[st][nn][ks*8 + lc]);
                bfr[nt][1] = cvt_tf32(Ws[st][nn][ks*8 + lc + 4]);
            }
            uint32_t afr[MT][4];
            #pragma unroll
            for (int mt = 0; mt < MT; mt++) {
                int rr = wmBase + mt*16 + lr;
                afr[mt][0] = cvt_tf32(As[st][rr][ks*8 + lc]);
                afr[mt][1] = cvt_tf32(As[st][rr + 8][ks*8 + lc]);
                afr[mt][2] = cvt_tf32(As[st][rr][ks*8 + lc + 4]);
                afr[mt][3] = cvt_tf32(As[st][rr + 8][ks*8 + lc + 4]);
            }
            #pragma unroll
            for (int mt = 0; mt < MT; mt++)
                #pragma unroll
                for (int nt = 0; nt < NT; nt++)
                    MMA_TF32(acc[mt][nt], afr[mt][0], afr[mt][1], afr[mt][2], afr[mt][3],
                             bfr[nt][0], bfr[nt][1]);
        }
        __syncthreads();
    }

    if (LNMODE == 0) {
        #pragma unroll
        for (int mt = 0; mt < MT; mt++) {
            #pragma unroll
            for (int nt = 0; nt < NT; nt++) {
                int row0 = rowBase + wmBase + mt*16 + lr;
                int col  = colBase + wnBase + nt*8 + 2*lc;
                float bx = 0.f, by = 0.f;
                if (bias) { bx = bias[col]; by = bias[col+1]; }
                float2 o0 = make_float2(acc[mt][nt][0] + bx, acc[mt][nt][1] + by);
                float2 o1 = make_float2(acc[mt][nt][2] + bx, acc[mt][nt][3] + by);
                if (relu) {
                    o0.x = fmaxf(o0.x, 0.f); o0.y = fmaxf(o0.y, 0.f);
                    o1.x = fmaxf(o1.x, 0.f); o1.y = fmaxf(o1.y, 0.f);
                }
                *reinterpret_cast<float2*>(C + (size_t)row0*Cout + col) = o0;
                *reinterpret_cast<float2*>(C + (size_t)(row0+8)*Cout + col) = o1;
            }
        }
    } else {
        float (*Cs)[BN + 4] = reinterpret_cast<float(*)[BN + 4]>(dsm);
        #pragma unroll
        for (int mt = 0; mt < MT; mt++) {
            #pragma unroll
            for (int nt = 0; nt < NT; nt++) {
                int r0 = wmBase + mt*16 + lr;
                int col = wnBase + nt*8 + 2*lc;
                float bx = bias[col], by = bias[col+1];
                *reinterpret_cast<float2*>(&Cs[r0][col]) =
                    make_float2(acc[mt][nt][0] + bx, acc[mt][nt][1] + by);
                *reinterpret_cast<float2*>(&Cs[r0 + 8][col]) =
                    make_float2(acc[mt][nt][2] + bx, acc[mt][nt][3] + by);
            }
        }
        __syncthreads();
        #pragma unroll
        for (int r = 0; r < BM/8; r++) {
            int row = wid * (BM/8) + r;
            float4 v = *reinterpret_cast<float4*>(&Cs[row][lane*4]);
            float s = v.x + v.y + v.z + v.w;
            float q = v.x*v.x + v.y*v.y + v.z*v.z + v.w*v.w;
            #pragma unroll
            for (int o = 16; o > 0; o >>= 1) {
                s += __shfl_xor_sync(0xffffffffu, s, o);
                q += __shfl_xor_sync(0xffffffffu, q, o);
            }
            float mu = s * (1.f/DIMF);
            float var = fmaxf(q * (1.f/DIMF) - mu*mu, 0.f);
            float rstd = rsqrtf(var + 1e-5f);
            int grow = rowBase + row;
            int rrow = gatherResid ? g_idxc[grow] : grow;
            float4 gv = *reinterpret_cast<const float4*>(lng + lane*4);
            float4 bv = *reinterpret_cast<const float4*>(lnb + lane*4);
            float4 rv = *reinterpret_cast<const float4*>(resid + (size_t)rrow*DIMF + lane*4);
            float4 o;
            o.x = (v.x - mu) * rstd * gv.x + bv.x + rv.x;
            o.y = (v.y - mu) * rstd * gv.y + bv.y + rv.y;
            o.z = (v.z - mu) * rstd * gv.z + bv.z + rv.z;
            o.w = (v.w - mu) * rstd * gv.w + bv.w + rv.w;
            *reinterpret_cast<float4*>(C + (size_t)grow*DIMF + lane*4) = o;
        }
    }
}

template<int BM, int BN, int WM, int WN, int BK, int NSTAGE>
__global__ __launch_bounds__(256, 3) void k_gemm(
    const float* __restrict__ A, const float* __restrict__ W,
    const float* __restrict__ bias, float* __restrict__ C,
    int Cin, int Cout, int relu)
{
    gemm_body<BM, BN, WM, WN, BK, NSTAGE, 0, 0>(A, W, bias, C, Cin, Cout, relu,
                                                nullptr, nullptr, nullptr, 0, nullptr);
}

template<int BM, int BN, int WM, int WN, int BK, int NSTAGE>
__global__ __launch_bounds__(256, 3) void k_gemm_ln(
    const float* __restrict__ A, const float* __restrict__ W,
    const float* __restrict__ bias, float* __restrict__ C, int Cin,
    const float* __restrict__ lng, const float* __restrict__ lnb,
    const float* __restrict__ resid, int gatherResid)
{
    gemm_body<BM, BN, WM, WN, BK, NSTAGE, 1, 0>(A, W, bias, C, Cin, DIMF, 0,
                                                lng, lnb, resid, gatherResid, nullptr);
}

// QKV merged: z=0 -> K, z=1 -> V (all points); z=2 -> Q over gathered centers.
struct P3 { const float* W[3]; float* C[3]; const long long* raw; };
__global__ __launch_bounds__(256, 3) void k_gemm_qkv(const float* __restrict__ A, P3 p)
{
    int z = blockIdx.z;
    if (z == 2) {
        if (blockIdx.x >= MC/64) return;
        gemm_body<64, 128, 32, 32, 32, 2, 0, 1>(A, p.W[2], nullptr, p.C[2], DIMF, DIMF, 0,
                                                nullptr, nullptr, nullptr, 0, p.raw);
    } else {
        gemm_body<64, 128, 32, 32, 32, 2, 0, 0>(A, p.W[z], nullptr, p.C[z], DIMF, DIMF, 0,
                                                nullptr, nullptr, nullptr, 0, nullptr);
    }
}

// smem byte counts (LDK=36)
#define GSMN(NS_, BM_, BN_) ((NS_) * ((BM_) + (BN_)) * 36 * 4)
static const int SM_QKV = GSMN(2,64,128);   // 55296
static const int SM_W1  = GSMN(3,64,128);   // 82944
static const int SM_LN  = GSMN(3,32,128) > (32*(128+4)*4) ? GSMN(3,32,128) : (32*(128+4)*4); // 69120
static const int SM_PREP = CPB*CAP*8;       // 32768

// ---------------- per-center attention ----------------
__global__ void k_attn() {
    __shared__ float q[DIMF];
    __shared__ float kS[KNB][DIMF + 4];
    __shared__ float vS[KNB][DIMF + 4];
    __shared__ int nbr_s[KNB];
    __shared__ int s_cnt;
    const int m = blockIdx.x, tid = threadIdx.x;
    if (tid < KNB) nbr_s[tid] = g_nbr[m*KNB + tid];
    if (tid == 0) s_cnt = g_cnt[m];
    q[tid] = g_Qc[(size_t)m*DIMF + tid] * 0.17677669529663687f;  // DH^-0.5
    __syncthreads();

    #pragma unroll
    for (int f = tid; f < KNB * (DIMF/4); f += 128) {
        int s = f >> 5, c4 = f & 31;
        size_t off = (size_t)nbr_s[s]*DIMF + c4*4;
        float4 kx = *reinterpret_cast<const float4*>(&g_Kp[off]);
        float4 vx = *reinterpret_cast<const float4*>(&g_Vp[off]);
        *reinterpret_cast<float4*>(&kS[s][c4*4]) = kx;
        *reinterpret_cast<float4*>(&vS[s][c4*4]) = vx;
    }
    __syncthreads();

    const int h = tid >> 5, lane = tid & 31;
    const int cnt = s_cnt;
    float logit = -1e9f;
    if (lane < cnt) {
        float a = 0.f;
        #pragma unroll
        for (int d = 0; d < DH; d++) a += q[h*DH + d] * kS[lane][h*DH + d];
        logit = a;
    }
    float mx = logit;
    #pragma unroll
    for (int o = 16; o > 0; o >>= 1) mx = fmaxf(mx, __shfl_xor_sync(0xffffffffu, mx, o));
    float e = (lane < cnt) ? expf(logit - mx) : 0.f;
    float sm = e;
    #pragma unroll
    for (int o = 16; o > 0; o >>= 1) sm += __shfl_xor_sync(0xffffffffu, sm, o);
    float w = e / sm;

    float acc = 0.f;
    #pragma unroll
    for (int kk = 0; kk < KNB; kk++)
        acc += __shfl_sync(0xffffffffu, w, kk) * vS[kk][h*DH + lane];
    g_ao[(size_t)m*DIMF + lane*NH + h] = acc;
}

// ---------------- final scatter ----------------
__global__ void k_scatter(const float* __restrict__ feats, float* __restrict__ out) {
    int i = blockIdx.x * 256 + threadIdx.x;
    int n = i >> 5, c4 = i & 31;
    int ctr = g_near[n];
    float4 f = *reinterpret_cast<const float4*>(feats + (size_t)n*DIMF + c4*4);
    float4 c = *reinterpret_cast<const float4*>(g_c2 + (size_t)ctr*DIMF + c4*4);
    f.x += c.x; f.y += c.y; f.z += c.z; f.w += c.w;
    *reinterpret_cast<float4*>(out + (size_t)n*DIMF + c4*4) = f;
}

// ---------------- launch ----------------
extern "C" void kernel_launch(void* const* d_in, const int* in_sizes, int n_in,
                              void* d_out, int out_size) {
    const float* xyz   = (const float*)d_in[0];
    const float* feats = (const float*)d_in[1];
    const long long* idxc = (const long long*)d_in[2];
    const float* Wq = (const float*)d_in[3];
    const float* Wk = (const float*)d_in[4];
    const float* Wv = (const float*)d_in[5];
    const float* Wo = (const float*)d_in[6];
    const float* bo = (const float*)d_in[7];
    const float* g1 = (const float*)d_in[8];
    const float* be1 = (const float*)d_in[9];
    const float* g2 = (const float*)d_in[10];
    const float* be2 = (const float*)d_in[11];
    const float* W1 = (const float*)d_in[12];
    const float* b1f = (const float*)d_in[13];
    const float* W2 = (const float*)d_in[14];
    const float* b2f = (const float*)d_in[15];
    float* out = (float*)d_out;

    float *qc, *kp, *vp, *ao, *c1, *hid, *c2;
    cudaGetSymbolAddress((void**)&qc,  g_Qc);
    cudaGetSymbolAddress((void**)&kp,  g_Kp);
    cudaGetSymbolAddress((void**)&vp,  g_Vp);
    cudaGetSymbolAddress((void**)&ao,  g_ao);
    cudaGetSymbolAddress((void**)&c1,  g_c1);
    cudaGetSymbolAddress((void**)&hid, g_hid);
    cudaGetSymbolAddress((void**)&c2,  g_c2);

    static cudaStream_t s1 = nullptr;
    static cudaEvent_t eFork = nullptr, ePrep = nullptr;
    if (!s1) {
        cudaStreamCreateWithFlags(&s1, cudaStreamNonBlocking);
        cudaEventCreateWithFlags(&eFork, cudaEventDisableTiming);
        cudaEventCreateWithFlags(&ePrep, cudaEventDisableTiming);
        cudaFuncSetAttribute(k_gemm_qkv,
            cudaFuncAttributeMaxDynamicSharedMemorySize, SM_QKV);
        cudaFuncSetAttribute(k_gemm<64,128,32,32,32,3>,
            cudaFuncAttributeMaxDynamicSharedMemorySize, SM_W1);
        cudaFuncSetAttribute(k_gemm_ln<32,128,16,32,32,3>,
            cudaFuncAttributeMaxDynamicSharedMemorySize, SM_LN);
    }
    cudaStream_t s0 = 0;

    // fork s1 from capture-origin stream, run prep parallel to QKV
    cudaEventRecord(eFork, s0);
    cudaStreamWaitEvent(s1, eFork, 0);
    k_prep<<<MC/CPB + NPTS/256, 256, SM_PREP, s1>>>(xyz, idxc);
    cudaEventRecord(ePrep, s1);

    P3 p;
    p.W[0] = Wk; p.W[1] = Wv; p.W[2] = Wq;
    p.C[0] = kp; p.C[1] = vp; p.C[2] = qc;
    p.raw = idxc;
    k_gemm_qkv<<<dim3(NPTS/64, 1, 3), 256, SM_QKV, s0>>>(feats, p);

    cudaStreamWaitEvent(s0, ePrep, 0);
    k_attn<<<MC, 128, 0, s0>>>();

    // Wo GEMM + LN1 + residual(feats gathered) -> c1   (128 blocks, 3-stage)
    k_gemm_ln<32,128,16,32,32,3><<<dim3(MC/32, 1), 256, SM_LN, s0>>>(
        ao, Wo, bo, c1, DIMF, g1, be1, feats, 1);
    // FFN up (relu)   (256 blocks, 3-stage)
    k_gemm<64,128,32,32,32,3><<<dim3(MC/64, HID/128), 256, SM_W1, s0>>>(
        c1, W1, b1f, hid, DIMF, HID, 1);
    // FFN down + LN2 + residual(c1) -> c2   (128 blocks, 3-stage)
    k_gemm_ln<32,128,16,32,32,3><<<dim3(MC/32, 1), 256, SM_LN, s0>>>(
        hid, W2, b2f, c2, HID, g2, be2, c1, 0);

    k_scatter<<<NPTS*(DIMF/4)/256, 256, 0, s0>>>(feats, out);
}